// round 12
// baseline (speedup 1.0000x reference)
#include <cuda_runtime.h>
#include <cuda_bf16.h>
#include <math.h>
#include <stdint.h>

// Problem dims (fixed by setup_inputs)
#define Bsz 512
#define Dsz 128
#define Isz 64
#define Hd  256           // decoder hidden
#define HeN 512           // encoder hidden
#define KeTOT (Isz + HeN) // 576

// ---------------- device scratch (static, no allocations) ----------------
__device__ __nv_bfloat16 g_We_hi[4 * HeN][KeTOT];  // [n'=u*4+g][k]
__device__ __nv_bfloat16 g_We_lo[4 * HeN][KeTOT];
__device__ __nv_bfloat16 g_Wd_hi[4 * Hd][Hd];
__device__ __nv_bfloat16 g_Wd_lo[4 * Hd][Hd];
__device__ __nv_bfloat16 g_Xe_hi[Dsz][Bsz][Isz];   // X_imp split, [t][m][k]
__device__ __nv_bfloat16 g_Xe_lo[Dsz][Bsz][Isz];
__device__ __nv_bfloat16 g_he_hi[2][Bsz][HeN];     // encoder h ping-pong (split)
__device__ __nv_bfloat16 g_he_lo[2][Bsz][HeN];
__device__ __nv_bfloat16 g_hd_hi[2][Bsz][Hd];      // decoder h ping-pong (split)
__device__ __nv_bfloat16 g_hd_lo[2][Bsz][Hd];
__device__ float g_c_d[Bsz * Hd];                  // decoder c0 (= z), read once
__device__ float g_hs[Dsz][Bsz * Hd];              // decoder h sequence fp32
__device__ unsigned int g_bar8_e[8][64];           // split step-barrier counters (256B stride)
__device__ unsigned int g_bar8_d[8][64];

__device__ __forceinline__ float sigm(float x) { return 1.0f / (1.0f + expf(-x)); }

// ---------------- low-level helpers ----------------
__device__ __forceinline__ uint32_t smem_u32(const void* p) {
    uint32_t a;
    asm("{ .reg .u64 t; cvta.to.shared.u64 t, %1; cvt.u32.u64 %0, t; }" : "=r"(a) : "l"(p));
    return a;
}
#define CP16(dst, src) \
    asm volatile("cp.async.cg.shared.global [%0], [%1], 16;" :: "r"(dst), "l"(src) : "memory")
#define CP_COMMIT() asm volatile("cp.async.commit_group;" ::: "memory")
#define CP_WAIT1()  asm volatile("cp.async.wait_group 1;" ::: "memory")
#define CP_WAIT0()  asm volatile("cp.async.wait_group 0;" ::: "memory")

__device__ __forceinline__ void ldsm4(uint32_t* d, uint32_t addr) {
    asm volatile("ldmatrix.sync.aligned.m8n8.x4.shared.b16 {%0,%1,%2,%3}, [%4];"
        : "=r"(d[0]), "=r"(d[1]), "=r"(d[2]), "=r"(d[3]) : "r"(addr));
}
__device__ __forceinline__ void mma16816(float* c, const uint32_t* a, uint32_t b0, uint32_t b1) {
    asm volatile("mma.sync.aligned.m16n8k16.row.col.f32.bf16.bf16.f32 "
        "{%0,%1,%2,%3}, {%4,%5,%6,%7}, {%8,%9}, {%0,%1,%2,%3};"
        : "+f"(c[0]), "+f"(c[1]), "+f"(c[2]), "+f"(c[3])
        : "r"(a[0]), "r"(a[1]), "r"(a[2]), "r"(a[3]), "r"(b0), "r"(b1));
}

// 128B-row tiles with XOR swizzle (Swizzle<3,4,3>): bits[6:4] ^= bits[9:7]
__device__ __forceinline__ uint32_t swz(uint32_t off) { return off ^ ((off >> 3) & 0x70); }

// ---- encoder persistent layout (K-chunks of 64) ----
#define E_WCH   16384                    // weight chunk: 64 rows x 128B, hi + lo
#define E_WS_SZ (9 * E_WCH)              // 147456 B resident weights
#define E_AST   32768                    // A stage: 128 rows x 128B, hi + lo
#define E_A0    E_WS_SZ
#define E_CONST (E_A0 + 2 * E_AST)       // 212992
#define E_SMEMP (E_CONST + 512)          // 213504 B
// ---- decoder persistent layout ----
#define D_WCH   16384
#define D_WS_SZ (4 * D_WCH)              // 65536 B
#define D_AST   16384                    // 64 rows x 128B, hi + lo
#define D_A0    D_WS_SZ
#define D_CONST (D_A0 + 2 * D_AST)       // 98304
#define D_SMEMP (D_CONST + 512)          // 98816 B
// epilogue pitch (floats); epilogue overlays the A-stage region
#define EPITCH 66
// ---- out_kernel layout: Hs 64x256 fp32 + Ws 256x64 fp32 ----
#define O_HS   0
#define O_WS   (64 * 256 * 4)            // 65536
#define O_SMEM (O_WS + 256 * 64 * 4)     // 131072

// ---------------- prep kernels ----------------
__global__ void conv_We_kernel(const float* __restrict__ Wx, const float* __restrict__ Wh) {
    int idx = blockIdx.x * 256 + threadIdx.x;
    if (idx >= 4 * HeN * KeTOT) return;
    int n = idx / KeTOT, k = idx % KeTOT;
    int u = n >> 2, g = n & 3, col = g * HeN + u;
    float w = (k < Isz) ? Wx[k * (4 * HeN) + col] : Wh[(k - Isz) * (4 * HeN) + col];
    __nv_bfloat16 hi = __float2bfloat16(w);
    g_We_hi[n][k] = hi;
    g_We_lo[n][k] = __float2bfloat16(w - __bfloat162float(hi));
}
__global__ void conv_Wd_kernel(const float* __restrict__ Wh) {
    int idx = blockIdx.x * 256 + threadIdx.x;
    if (idx >= 4 * Hd * Hd) return;
    int n = idx / Hd, k = idx % Hd;
    int u = n >> 2, g = n & 3, col = g * Hd + u;
    float w = Wh[k * (4 * Hd) + col];
    __nv_bfloat16 hi = __float2bfloat16(w);
    g_Wd_hi[n][k] = hi;
    g_Wd_lo[n][k] = __float2bfloat16(w - __bfloat162float(hi));
}
__global__ void conv_X_kernel(const float* __restrict__ X, const float* __restrict__ Wm,
                              const float* __restrict__ A) {
    int idx = blockIdx.x * 256 + threadIdx.x;
    if (idx >= Dsz * Bsz * Isz) return;
    int t = idx / (Bsz * Isz);
    int r = idx % (Bsz * Isz);
    int m = r / Isz, k = r % Isz;
    int src = (m * Dsz + t) * Isz + k;
    float w = Wm[src];
    float v = X[src] * w + A[t * Isz + k] * (1.0f - w);
    __nv_bfloat16 hi = __float2bfloat16(v);
    g_Xe_hi[t][m][k] = hi;
    g_Xe_lo[t][m][k] = __float2bfloat16(v - __bfloat162float(hi));
}
__global__ void init_enc_kernel() {
    int i = blockIdx.x * 256 + threadIdx.x;
    if (i < 8) { g_bar8_e[i][0] = 0u; g_bar8_d[i][0] = 0u; }
    if (i >= Bsz * HeN) return;
    __nv_bfloat16 z = __float2bfloat16(0.0f);
    (&g_he_hi[0][0][0])[i] = z;
    (&g_he_lo[0][0][0])[i] = z;
}

// ---------------- small outputs ----------------
__global__ void small_kernel(const float* __restrict__ mu_c_raw,
                             const float* __restrict__ sig_lat,
                             const float* __restrict__ phi_lat,
                             float* __restrict__ out_muc,
                             float* __restrict__ out_sig,
                             float* __restrict__ out_phi) {
    int tid = threadIdx.x;
    for (int i = tid; i < 8 * Hd; i += blockDim.x) {
        out_muc[i] = mu_c_raw[i];
        float v = sig_lat[i];
        out_sig[i] = fmaxf(v, 0.0f) + log1pf(expf(-fabsf(v)));
    }
    if (tid == 0) {
        float m = -1e30f;
        for (int i = 0; i < 8; ++i) m = fmaxf(m, phi_lat[i]);
        float e[8]; float s = 0.0f;
        for (int i = 0; i < 8; ++i) { e[i] = expf(phi_lat[i] - m); s += e[i]; }
        float inv = 1.0f / s;
        for (int i = 0; i < 8; ++i) out_phi[i] = e[i] * inv;
    }
}

// ============================================================================
// Persistent encoder: grid (4, 32), 256 threads (8 warps), 1 CTA/SM.
// CTA tile M=128, N=64. Warp: rows (wid&3)*32, cols (wid>>2)*32.
// K-chunks of 64 (9 chunks: X=0, h=1..8). Swizzled 128B-row tiles.
// Weights SMEM-resident; c register-resident.
// Step barrier: 8 split counters; wait overlapped with X-chunk compute.
// ============================================================================
__global__ void __launch_bounds__(256, 1) enc_persist(
    const float* __restrict__ bias,
    const float* __restrict__ wci, const float* __restrict__ wcf,
    const float* __restrict__ wco) {
    extern __shared__ char smem[];
    const uint32_t sb = smem_u32(smem);
    const int tid = threadIdx.x, wid = tid >> 5, lane = tid & 31;
    const int rw = wid & 3, cw = wid >> 2;
    const int bm0 = blockIdx.x * 128;
    const int n0  = blockIdx.y * 64;
    const int U0  = n0 >> 2;
    const int myid = blockIdx.y * 4 + blockIdx.x;   // 0..127

    // ---- one-time: resident weight slab (9 chunks of 64 rows x 64 k, hi+lo) ----
#pragma unroll
    for (int c = 0; c < 9; ++c) {
        uint32_t wb = sb + c * E_WCH;
#pragma unroll
        for (int j = 0; j < 2; ++j) {
            int flat = tid + j * 256;       // 0..511
            int row = flat >> 3, c16 = flat & 7;
            uint32_t off = swz(row * 128 + c16 * 16);
            CP16(wb + off,        &g_We_hi[n0 + row][c * 64 + c16 * 8]);
            CP16(wb + 8192 + off, &g_We_lo[n0 + row][c * 64 + c16 * 8]);
        }
    }
    CP_COMMIT();
    // ---- one-time: gate constants to smem ----
    float* csm = (float*)(smem + E_CONST);
    if (tid < 16) {
        int u = U0 + tid;
        csm[tid]      = bias[u];
        csm[16 + tid] = bias[HeN + u];
        csm[32 + tid] = bias[2 * HeN + u];
        csm[48 + tid] = bias[3 * HeN + u];
        csm[64 + tid] = wci[u];
        csm[80 + tid] = wcf[u];
        csm[96 + tid] = wco[u];
    }
    CP_WAIT0();
    __syncthreads();

    // A-issue: 128 rows x 64 k (hi+lo), 4 iterations of 256 threads
#define E_AISSUE(ah_, al_, ap_, kb_, s_) do { \
        uint32_t so_ = sb + E_A0 + (s_) * E_AST; \
        _Pragma("unroll") \
        for (int j = 0; j < 4; ++j) { \
            int flat = tid + j * 256; \
            int row = flat >> 3, c16 = flat & 7; \
            uint32_t off = swz(row * 128 + c16 * 16); \
            CP16(so_ + off,         (ah_) + (bm0 + row) * (ap_) + (kb_) + c16 * 8); \
            CP16(so_ + 16384 + off, (al_) + (bm0 + row) * (ap_) + (kb_) + c16 * 8); \
        } \
    } while (0)

    // one K64 chunk of 3-pass split-bf16 HMMA from stage so_/weights wb_
#define E_COMPUTE(so_, wb_) do { \
        _Pragma("unroll") \
        for (int ks = 0; ks < 4; ++ks) { \
            uint32_t Ah[2][4], Al[2][4], Bh[2][4], Bl[2][4]; \
            _Pragma("unroll") \
            for (int mt = 0; mt < 2; ++mt) { \
                uint32_t ra = (so_) + (uint32_t)(rw * 32 + mt * 16 + a_row) * 128 \
                            + (((uint32_t)(ks * 32 + a_kb)) ^ lxor); \
                ldsm4(Ah[mt], ra); \
                ldsm4(Al[mt], ra + 16384); \
            } \
            _Pragma("unroll") \
            for (int np = 0; np < 2; ++np) { \
                uint32_t rb = (wb_) + (uint32_t)(cw * 32 + np * 16 + b_row) * 128 \
                            + (((uint32_t)(ks * 32 + b_kb)) ^ lxor); \
                ldsm4(Bh[np], rb); \
                ldsm4(Bl[np], rb + 8192); \
            } \
            _Pragma("unroll") \
            for (int mt = 0; mt < 2; ++mt) \
                _Pragma("unroll") \
                for (int np = 0; np < 2; ++np) { \
                    mma16816(acc[mt][2 * np],     Ah[mt], Bh[np][0], Bh[np][1]); \
                    mma16816(acc[mt][2 * np + 1], Ah[mt], Bh[np][2], Bh[np][3]); \
                    mma16816(acc[mt][2 * np],     Ah[mt], Bl[np][0], Bl[np][1]); \
                    mma16816(acc[mt][2 * np + 1], Ah[mt], Bl[np][2], Bl[np][3]); \
                    mma16816(acc[mt][2 * np],     Al[mt], Bh[np][0], Bh[np][1]); \
                    mma16816(acc[mt][2 * np + 1], Al[mt], Bh[np][2], Bh[np][3]); \
                } \
        } \
    } while (0)

    // prefetch X chunk of step 0 into stage 0
    E_AISSUE((&g_Xe_hi[0][0][0]), (&g_Xe_lo[0][0][0]), Isz, 0, 0);
    CP_COMMIT();

    // ldmatrix per-lane address components
    const int a_row = (lane & 7) + ((lane >> 3) & 1) * 8;
    const int a_kb  = ((lane >> 4) & 1) * 16;
    const int b_row = (lane & 7) + (lane >> 4) * 8;
    const int b_kb  = ((lane >> 3) & 1) * 16;
    const uint32_t lxor = (uint32_t)((lane & 7) << 4);   // swizzle xor (row low bits)
    float* epi = (float*)(smem + E_A0);

    // register-resident cell state: thread owns (row = tid&127, units U0+uh*8..+8)
    float creg[8] = {0.f, 0.f, 0.f, 0.f, 0.f, 0.f, 0.f, 0.f};

    for (int t = 0; t < Dsz; ++t) {
        const int buf = t & 1;
        const __nv_bfloat16* __restrict__ hhi = &g_he_hi[buf][0][0];
        const __nv_bfloat16* __restrict__ hlo = &g_he_lo[buf][0][0];

        float acc[2][4][4];
#pragma unroll
        for (int mt = 0; mt < 2; ++mt)
#pragma unroll
            for (int nt = 0; nt < 4; ++nt)
#pragma unroll
                for (int r = 0; r < 4; ++r) acc[mt][nt][r] = 0.0f;

        // ---- chunk 0 (X): independent of h(t) -> compute before barrier wait ----
        CP_WAIT0();
        __syncthreads();
        E_COMPUTE(sb + E_A0, sb);

        // ---- barrier wait (h(t) ready); overlapped with chunk-0 compute above ----
        if (t > 0) {
            if (tid < 8) {
                unsigned int tgt = 16u * (unsigned int)t;
                while (*(volatile unsigned int*)&g_bar8_e[tid][0] < tgt) { }
                __threadfence();
            }
        }
        __syncthreads();     // barrier confirmed; also: all warps done reading stage 0

        // stream h chunks 1..8 (2-stage pipeline)
        E_AISSUE(hhi, hlo, HeN, 0, 1);  CP_COMMIT();   // chunk 1 -> stage 1
        E_AISSUE(hhi, hlo, HeN, 64, 0); CP_COMMIT();   // chunk 2 -> stage 0

        for (int c = 1; c <= 8; ++c) {
            CP_WAIT1();
            __syncthreads();
            E_COMPUTE(sb + E_A0 + (c & 1) * E_AST, sb + c * E_WCH);
            __syncthreads();
            if (c + 2 <= 8) {
                E_AISSUE(hhi, hlo, HeN, (c + 1) * 64, (c & 1));
            }
            CP_COMMIT();
        }

        // ---- epilogue: fragments -> smem (overlays A region) ----
#pragma unroll
        for (int mt = 0; mt < 2; ++mt)
#pragma unroll
            for (int nt = 0; nt < 4; ++nt) {
                int r0 = rw * 32 + mt * 16 + (lane >> 2);
                int c0 = cw * 32 + nt * 8 + (lane & 3) * 2;
                epi[r0 * EPITCH + c0]           = acc[mt][nt][0];
                epi[r0 * EPITCH + c0 + 1]       = acc[mt][nt][1];
                epi[(r0 + 8) * EPITCH + c0]     = acc[mt][nt][2];
                epi[(r0 + 8) * EPITCH + c0 + 1] = acc[mt][nt][3];
            }
        __syncthreads();

        // ---- pointwise: thread = (row = tid&127, unit-half = tid>>7) ----
        const int row = tid & 127;
        const int uh  = tid >> 7;
        const int grow = bm0 + row;
        alignas(16) unsigned short hh16[8], hl16[8];
#pragma unroll
        for (int j = 0; j < 8; ++j) {
            int ui = uh * 8 + j;
            float c_old = creg[j];
            float zi = epi[row * EPITCH + 4 * ui + 0] + csm[ui];
            float zf = epi[row * EPITCH + 4 * ui + 1] + csm[16 + ui];
            float zg = epi[row * EPITCH + 4 * ui + 2] + csm[32 + ui];
            float zo = epi[row * EPITCH + 4 * ui + 3] + csm[48 + ui];
            float ig = sigm(zi + c_old * csm[64 + ui]);
            float fg = sigm(zf + c_old * csm[80 + ui]);
            float cn = fg * c_old + ig * tanhf(zg);
            float og = sigm(zo + cn * csm[96 + ui]);
            float h  = og * tanhf(cn);
            creg[j] = cn;
            __nv_bfloat16 hb = __float2bfloat16(h);
            hh16[j] = __bfloat16_as_ushort(hb);
            hl16[j] = __bfloat16_as_ushort(__float2bfloat16(h - __bfloat162float(hb)));
        }
        *(uint4*)&g_he_hi[buf ^ 1][grow][U0 + uh * 8] = ((uint4*)hh16)[0];
        *(uint4*)&g_he_lo[buf ^ 1][grow][U0 + uh * 8] = ((uint4*)hl16)[0];

        // ---- publish completion (split counters), then prefetch next X ----
        __threadfence();
        __syncthreads();     // h stores fenced; all epi reads done
        if (t + 1 < Dsz) {
            if (tid == 0) atomicAdd(&g_bar8_e[myid & 7][0], 1u);
            E_AISSUE((&g_Xe_hi[t + 1][0][0]), (&g_Xe_lo[t + 1][0][0]), Isz, 0, 0);
            CP_COMMIT();
        }
    }
#undef E_AISSUE
#undef E_COMPUTE
}

// ---------------- latent z + decoder init ----------------
__global__ void z_kernel(const float* __restrict__ noise,
                         float* __restrict__ out_z,
                         float* __restrict__ out_mu,
                         float* __restrict__ out_ls) {
    int idx = blockIdx.x * blockDim.x + threadIdx.x;
    if (idx >= Bsz * Hd) return;
    int b = idx >> 8;
    int u = idx & 255;
    float mu = __bfloat162float(g_he_hi[0][b][u]) + __bfloat162float(g_he_lo[0][b][u]);
    float ls = __bfloat162float(g_he_hi[0][b][Hd + u]) + __bfloat162float(g_he_lo[0][b][Hd + u]);
    float zz = mu + expf(0.5f * ls) * noise[idx];
    out_mu[idx] = mu;
    out_ls[idx] = ls;
    out_z[idx]  = zz;
    g_c_d[idx]  = zz;
}

// ============================================================================
// Persistent decoder: grid (8, 16), 256 threads (8 warps), 1 CTA/SM.
// CTA tile M=64, N=64. Warp: rows (wid&1)*32, cols (wid>>1)*16. Inputs zero.
// K-chunks of 64 (4 chunks). Swizzled 128B tiles. c register-resident.
// Split-counter step barrier.
// ============================================================================
__global__ void __launch_bounds__(256, 1) dec_persist(
    const float* __restrict__ bias,
    const float* __restrict__ wci, const float* __restrict__ wcf,
    const float* __restrict__ wco) {
    extern __shared__ char smem[];
    const uint32_t sb = smem_u32(smem);
    const int tid = threadIdx.x, wid = tid >> 5, lane = tid & 31;
    const int rw = wid & 1, cw = wid >> 1;
    const int bm0 = blockIdx.x * 64;
    const int n0  = blockIdx.y * 64;
    const int U0  = n0 >> 2;
    const int myid = blockIdx.y * 8 + blockIdx.x;   // 0..127

    // ---- one-time: resident weight slab (4 chunks) ----
#pragma unroll
    for (int c = 0; c < 4; ++c) {
        uint32_t wb = sb + c * D_WCH;
#pragma unroll
        for (int j = 0; j < 2; ++j) {
            int flat = tid + j * 256;
            int row = flat >> 3, c16 = flat & 7;
            uint32_t off = swz(row * 128 + c16 * 16);
            CP16(wb + off,        &g_Wd_hi[n0 + row][c * 64 + c16 * 8]);
            CP16(wb + 8192 + off, &g_Wd_lo[n0 + row][c * 64 + c16 * 8]);
        }
    }
    CP_COMMIT();
    float* csm = (float*)(smem + D_CONST);
    if (tid < 16) {
        int u = U0 + tid;
        csm[tid]      = bias[u];
        csm[16 + tid] = bias[Hd + u];
        csm[32 + tid] = bias[2 * Hd + u];
        csm[48 + tid] = bias[3 * Hd + u];
        csm[64 + tid] = wci[u];
        csm[80 + tid] = wcf[u];
        csm[96 + tid] = wco[u];
    }
    CP_WAIT0();
    __syncthreads();

    const int a_row = (lane & 7) + ((lane >> 3) & 1) * 8;
    const int a_kb  = ((lane >> 4) & 1) * 16;
    const int b_row = (lane & 7) + (lane >> 4) * 8;
    const int b_kb  = ((lane >> 3) & 1) * 16;
    const uint32_t lxor = (uint32_t)((lane & 7) << 4);
    float* epi = (float*)(smem + D_A0);

    // register-resident c: thread owns (row = tid&63, units U0+uq*4..+4); c0 = z
    const int prow = tid & 63;
    const int puq  = tid >> 6;
    const int pgrow = bm0 + prow;
    const int pub = puq * 4;
    float creg[4];
    {
        float4 v = *(float4*)&g_c_d[pgrow * Hd + U0 + pub];
        creg[0] = v.x; creg[1] = v.y; creg[2] = v.z; creg[3] = v.w;
    }

    for (int t = 0; t < Dsz; ++t) {
        const int buf = t & 1;
        if (t > 0) {
            const __nv_bfloat16* __restrict__ hhi = &g_hd_hi[buf][0][0];
            const __nv_bfloat16* __restrict__ hlo = &g_hd_lo[buf][0][0];

#define D_AISSUE(c, s) do { \
            uint32_t so_ = sb + D_A0 + (s) * D_AST; \
            int kb_ = (c) * 64; \
            _Pragma("unroll") \
            for (int j = 0; j < 2; ++j) { \
                int flat = tid + j * 256; \
                int row = flat >> 3, c16 = flat & 7; \
                uint32_t off = swz(row * 128 + c16 * 16); \
                CP16(so_ + off,        hhi + (bm0 + row) * Hd + kb_ + c16 * 8); \
                CP16(so_ + 8192 + off, hlo + (bm0 + row) * Hd + kb_ + c16 * 8); \
            } \
        } while (0)

            float acc[2][2][4];
#pragma unroll
            for (int mt = 0; mt < 2; ++mt)
#pragma unroll
                for (int nt = 0; nt < 2; ++nt)
#pragma unroll
                    for (int r = 0; r < 4; ++r) acc[mt][nt][r] = 0.0f;

            D_AISSUE(0, 0); CP_COMMIT();
            D_AISSUE(1, 1); CP_COMMIT();

            for (int c = 0; c < 4; ++c) {
                CP_WAIT1();
                __syncthreads();
                const uint32_t so = sb + D_A0 + (c & 1) * D_AST;
                const uint32_t wb = sb + c * D_WCH;
#pragma unroll
                for (int ks = 0; ks < 4; ++ks) {
                    uint32_t Ah[2][4], Al[2][4], Bh[4], Bl[4];
#pragma unroll
                    for (int mt = 0; mt < 2; ++mt) {
                        uint32_t ra = so + (uint32_t)(rw * 32 + mt * 16 + a_row) * 128
                                    + (((uint32_t)(ks * 32 + a_kb)) ^ lxor);
                        ldsm4(Ah[mt], ra);
                        ldsm4(Al[mt], ra + 8192);
                    }
                    uint32_t rb = wb + (uint32_t)(cw * 16 + b_row) * 128
                                + (((uint32_t)(ks * 32 + b_kb)) ^ lxor);
                    ldsm4(Bh, rb);
                    ldsm4(Bl, rb + 8192);
#pragma unroll
                    for (int mt = 0; mt < 2; ++mt) {
                        mma16816(acc[mt][0], Ah[mt], Bh[0], Bh[1]);
                        mma16816(acc[mt][1], Ah[mt], Bh[2], Bh[3]);
                        mma16816(acc[mt][0], Ah[mt], Bl[0], Bl[1]);
                        mma16816(acc[mt][1], Ah[mt], Bl[2], Bl[3]);
                        mma16816(acc[mt][0], Al[mt], Bh[0], Bh[1]);
                        mma16816(acc[mt][1], Al[mt], Bh[2], Bh[3]);
                    }
                }
                __syncthreads();
                if (c + 2 <= 3) { D_AISSUE(c + 2, c & 1); }
                CP_COMMIT();
            }
#undef D_AISSUE
            CP_WAIT0();
            __syncthreads();
#pragma unroll
            for (int mt = 0; mt < 2; ++mt)
#pragma unroll
                for (int nt = 0; nt < 2; ++nt) {
                    int r0 = rw * 32 + mt * 16 + (lane >> 2);
                    int c0 = cw * 16 + nt * 8 + (lane & 3) * 2;
                    epi[r0 * EPITCH + c0]           = acc[mt][nt][0];
                    epi[r0 * EPITCH + c0 + 1]       = acc[mt][nt][1];
                    epi[(r0 + 8) * EPITCH + c0]     = acc[mt][nt][2];
                    epi[(r0 + 8) * EPITCH + c0 + 1] = acc[mt][nt][3];
                }
            __syncthreads();
        }

        // ---- pointwise (register c) ----
        float* hsp = &g_hs[t][pgrow * Hd + U0 + pub];
        float hf[4];
        alignas(8) unsigned short hh16[4], hl16[4];
#pragma unroll
        for (int j = 0; j < 4; ++j) {
            int ui = pub + j;
            float c_old = creg[j];
            float zi = 0.f, zf = 0.f, zg = 0.f, zo = 0.f;
            if (t > 0) {
                zi = epi[prow * EPITCH + 4 * ui + 0];
                zf = epi[prow * EPITCH + 4 * ui + 1];
                zg = epi[prow * EPITCH + 4 * ui + 2];
                zo = epi[prow * EPITCH + 4 * ui + 3];
            }
            zi += csm[ui]; zf += csm[16 + ui]; zg += csm[32 + ui]; zo += csm[48 + ui];
            float ig = sigm(zi + c_old * csm[64 + ui]);
            float fg = sigm(zf + c_old * csm[80 + ui]);
            float cn = fg * c_old + ig * tanhf(zg);
            float og = sigm(zo + cn * csm[96 + ui]);
            float h  = og * tanhf(cn);
            creg[j] = cn; hf[j] = h;
            __nv_bfloat16 hb = __float2bfloat16(h);
            hh16[j] = __bfloat16_as_ushort(hb);
            hl16[j] = __bfloat16_as_ushort(__float2bfloat16(h - __bfloat162float(hb)));
        }
        *(float4*)hsp = make_float4(hf[0], hf[1], hf[2], hf[3]);
        *(uint2*)&g_hd_hi[buf ^ 1][pgrow][U0 + pub] = ((uint2*)hh16)[0];
        *(uint2*)&g_hd_lo[buf ^ 1][pgrow][U0 + pub] = ((uint2*)hl16)[0];

        if (t + 1 < Dsz) {
            // ---- split-counter step barrier ----
            __threadfence();
            __syncthreads();
            if (tid == 0) atomicAdd(&g_bar8_d[myid & 7][0], 1u);
            if (tid < 8) {
                unsigned int tgt = 16u * (unsigned int)(t + 1);
                while (*(volatile unsigned int*)&g_bar8_d[tid][0] < tgt) { }
                __threadfence();
            }
            __syncthreads();
        }
    }
}

// ---------------- output projection: hs @ Wout + bout, sigmoid ----------------
// grid (Dsz, 8), 256 threads, 128KB dynamic smem. Block: 64 rows x 64 cols.
// Thread: 4 rows x 4 cols. Wout + h tile staged in smem.
__global__ __launch_bounds__(256) void out_kernel(
    const float* __restrict__ Wout, const float* __restrict__ bout,
    float* __restrict__ out_x, float* __restrict__ out_xraw) {
    extern __shared__ char smem[];
    float* Hs = (float*)(smem + O_HS);   // [64][256]
    float* Ws = (float*)(smem + O_WS);   // [256][64]
    const int t  = blockIdx.x;
    const int b0 = blockIdx.y * 64;
    const int tid = threadIdx.x;

    const float4* __restrict__ hsrc = (const float4*)(&g_hs[t][b0 * Hd]);
    const float4* __restrict__ wsrc = (const float4*)Wout;
#pragma unroll
    for (int j = 0; j < 16; ++j) {
        int flat = tid + j * 256;          // 0..4095 float4 slots
        ((float4*)Hs)[flat] = hsrc[flat];
        ((float4*)Ws)[flat] = wsrc[flat];
    }
    __syncthreads();

    const int cx = tid & 15;               // col group: cols cx*4..+4
    const int ry = tid >> 4;               // row group: rows ry*4..+4
    float acc[4][4];
#pragma unroll
    for (int i = 0; i < 4; ++i)
#pragma unroll
        for (int j = 0; j < 4; ++j) acc[i][j] = 0.0f;

    for (int k = 0; k < 256; ++k) {
        float4 w = *(float4*)&Ws[k * 64 + cx * 4];
#pragma unroll
        for (int i = 0; i < 4; ++i) {
            float h = Hs[(ry * 4 + i) * 256 + k];
            acc[i][0] += h * w.x;
            acc[i][1] += h * w.y;
            acc[i][2] += h * w.z;
            acc[i][3] += h * w.w;
        }
    }
    float4 bo = *(const float4*)&bout[cx * 4];
#pragma unroll
    for (int i = 0; i < 4; ++i) {
        int row = b0 + ry * 4 + i;
        int oi = (row * Dsz + t) * Isz + cx * 4;
        float4 xr = make_float4(acc[i][0] + bo.x, acc[i][1] + bo.y,
                                acc[i][2] + bo.z, acc[i][3] + bo.w);
        *(float4*)&out_xraw[oi] = xr;
        float4 xs;
        xs.x = 1.0f / (1.0f + expf(-xr.x));
        xs.y = 1.0f / (1.0f + expf(-xr.y));
        xs.z = 1.0f / (1.0f + expf(-xr.z));
        xs.w = 1.0f / (1.0f + expf(-xr.w));
        *(float4*)&out_x[oi] = xs;
    }
}

// ---------------- launch ----------------
extern "C" void kernel_launch(void* const* d_in, const int* in_sizes, int n_in,
                              void* d_out, int out_size) {
    (void)in_sizes; (void)n_in; (void)out_size;
    const float* X      = (const float*)d_in[0];
    const float* Wm     = (const float*)d_in[1];
    const float* noise  = (const float*)d_in[2];
    const float* A      = (const float*)d_in[3];
    const float* Wx_e   = (const float*)d_in[4];
    const float* Wh_e   = (const float*)d_in[5];
    const float* b_e    = (const float*)d_in[6];
    const float* wci_e  = (const float*)d_in[7];
    const float* wcf_e  = (const float*)d_in[8];
    const float* wco_e  = (const float*)d_in[9];
    // d_in[10] = Wx_d : unused (decoder inputs are zero)
    const float* Wh_d   = (const float*)d_in[11];
    const float* b_d    = (const float*)d_in[12];
    const float* wci_d  = (const float*)d_in[13];
    const float* wcf_d  = (const float*)d_in[14];
    const float* wco_d  = (const float*)d_in[15];
    const float* Wout   = (const float*)d_in[16];
    const float* bout   = (const float*)d_in[17];
    const float* mu_c_r = (const float*)d_in[18];
    const float* sig_l  = (const float*)d_in[19];
    const float* phi_l  = (const float*)d_in[20];

    float* out = (float*)d_out;
    float* out_x    = out;                 // 4194304
    float* out_xraw = out + 4194304;       // 4194304
    float* out_muc  = out + 8388608;       // 2048
    float* out_sig  = out + 8390656;       // 2048
    float* out_phi  = out + 8392704;       // 8
    float* out_z    = out + 8392712;       // 131072
    float* out_mu   = out + 8523784;       // 131072
    float* out_ls   = out + 8654856;       // 131072

    cudaFuncSetAttribute(enc_persist, cudaFuncAttributeMaxDynamicSharedMemorySize, E_SMEMP);
    cudaFuncSetAttribute(dec_persist, cudaFuncAttributeMaxDynamicSharedMemorySize, D_SMEMP);
    cudaFuncSetAttribute(out_kernel,  cudaFuncAttributeMaxDynamicSharedMemorySize, O_SMEM);

    conv_We_kernel<<<(4 * HeN * KeTOT + 255) / 256, 256>>>(Wx_e, Wh_e);
    conv_Wd_kernel<<<(4 * Hd * Hd + 255) / 256, 256>>>(Wh_d);
    conv_X_kernel<<<(Dsz * Bsz * Isz + 255) / 256, 256>>>(X, Wm, A);
    init_enc_kernel<<<(Bsz * HeN + 255) / 256, 256>>>();
    small_kernel<<<1, 256>>>(mu_c_r, sig_l, phi_l, out_muc, out_sig, out_phi);

    enc_persist<<<dim3(4, 32), 256, E_SMEMP>>>(b_e, wci_e, wcf_e, wco_e);

    z_kernel<<<(Bsz * Hd + 255) / 256, 256>>>(noise, out_z, out_mu, out_ls);

    dec_persist<<<dim3(8, 16), 256, D_SMEMP>>>(b_d, wci_d, wcf_d, wco_d);

    out_kernel<<<dim3(Dsz, 8), 256, O_SMEM>>>(Wout, bout, out_x, out_xraw);
}

// round 13
// speedup vs baseline: 1.1235x; 1.1235x over previous
#include <cuda_runtime.h>
#include <cuda_bf16.h>
#include <math.h>
#include <stdint.h>

// Problem dims (fixed by setup_inputs)
#define Bsz 512
#define Dsz 128
#define Isz 64
#define Hd  256           // decoder hidden
#define HeN 512           // encoder hidden
#define KeTOT (Isz + HeN) // 576

// ---------------- device scratch (static, no allocations) ----------------
__device__ __nv_bfloat16 g_We_hi[4 * HeN][KeTOT];  // [n'=u*4+g][k]
__device__ __nv_bfloat16 g_We_lo[4 * HeN][KeTOT];
__device__ __nv_bfloat16 g_Wd_hi[4 * Hd][Hd];
__device__ __nv_bfloat16 g_Wd_lo[4 * Hd][Hd];
__device__ __nv_bfloat16 g_Xe_hi[Dsz][Bsz][Isz];   // X_imp split, [t][m][k]
__device__ __nv_bfloat16 g_Xe_lo[Dsz][Bsz][Isz];
__device__ __nv_bfloat16 g_he_hi[2][Bsz][HeN];     // encoder h ping-pong (split)
__device__ __nv_bfloat16 g_he_lo[2][Bsz][HeN];
__device__ __nv_bfloat16 g_hd_hi[2][Bsz][Hd];      // decoder h ping-pong (split)
__device__ __nv_bfloat16 g_hd_lo[2][Bsz][Hd];
__device__ float g_c_d[Bsz * Hd];                  // decoder c0 (= z), read once
__device__ float g_hs[Dsz][Bsz * Hd];              // decoder h sequence fp32
__device__ unsigned int g_bar_e;                   // persistent-kernel step barriers
__device__ unsigned int g_bar_d;

// fast transcendentals (error ~1e-6 rel; budget is 1e-3, current rel_err 8e-6)
__device__ __forceinline__ float sigm(float x) {
    return __fdividef(1.0f, 1.0f + __expf(-x));
}
__device__ __forceinline__ float tanh_fast(float x) {
    // 1 - 2/(e^{2x}+1); saturates correctly: e^{2x}->inf => 1, ->0 => -1
    return 1.0f - __fdividef(2.0f, __expf(2.0f * x) + 1.0f);
}

// ---------------- low-level helpers ----------------
__device__ __forceinline__ uint32_t smem_u32(const void* p) {
    uint32_t a;
    asm("{ .reg .u64 t; cvta.to.shared.u64 t, %1; cvt.u32.u64 %0, t; }" : "=r"(a) : "l"(p));
    return a;
}
#define CP16(dst, src) \
    asm volatile("cp.async.cg.shared.global [%0], [%1], 16;" :: "r"(dst), "l"(src) : "memory")
#define CP_COMMIT() asm volatile("cp.async.commit_group;" ::: "memory")
#define CP_WAIT1()  asm volatile("cp.async.wait_group 1;" ::: "memory")
#define CP_WAIT0()  asm volatile("cp.async.wait_group 0;" ::: "memory")

__device__ __forceinline__ void ldsm4(uint32_t* d, uint32_t addr) {
    asm volatile("ldmatrix.sync.aligned.m8n8.x4.shared.b16 {%0,%1,%2,%3}, [%4];"
        : "=r"(d[0]), "=r"(d[1]), "=r"(d[2]), "=r"(d[3]) : "r"(addr));
}
__device__ __forceinline__ void mma16816(float* c, const uint32_t* a, uint32_t b0, uint32_t b1) {
    asm volatile("mma.sync.aligned.m16n8k16.row.col.f32.bf16.bf16.f32 "
        "{%0,%1,%2,%3}, {%4,%5,%6,%7}, {%8,%9}, {%0,%1,%2,%3};"
        : "+f"(c[0]), "+f"(c[1]), "+f"(c[2]), "+f"(c[3])
        : "r"(a[0]), "r"(a[1]), "r"(a[2]), "r"(a[3]), "r"(b0), "r"(b1));
}

// 128B-row tiles with XOR swizzle (Swizzle<3,4,3>): bits[6:4] ^= bits[9:7]
__device__ __forceinline__ uint32_t swz(uint32_t off) { return off ^ ((off >> 3) & 0x70); }

// ---- encoder persistent layout (K-chunks of 64) ----
#define E_WCH   16384                    // weight chunk: 64 rows x 128B, hi + lo
#define E_WS_SZ (9 * E_WCH)              // 147456 B resident weights
#define E_AST   32768                    // A stage: 128 rows x 128B, hi + lo
#define E_A0    E_WS_SZ
#define E_CONST (E_A0 + 2 * E_AST)       // 212992
#define E_SMEMP (E_CONST + 512)          // 213504 B
// ---- decoder persistent layout ----
#define D_WCH   16384
#define D_WS_SZ (4 * D_WCH)              // 65536 B
#define D_AST   16384                    // 64 rows x 128B, hi + lo
#define D_A0    D_WS_SZ
#define D_CONST (D_A0 + 2 * D_AST)       // 98304
#define D_SMEMP (D_CONST + 512)          // 98816 B
// epilogue pitch (floats); epilogue overlays the A-stage region
#define EPITCH 66
// ---- out_kernel layout: Hs 64x256 fp32 + Ws 256x64 fp32 ----
#define O_HS   0
#define O_WS   (64 * 256 * 4)            // 65536
#define O_SMEM (O_WS + 256 * 64 * 4)     // 131072

// ---------------- prep kernels ----------------
__global__ void conv_We_kernel(const float* __restrict__ Wx, const float* __restrict__ Wh) {
    int idx = blockIdx.x * 256 + threadIdx.x;
    if (idx >= 4 * HeN * KeTOT) return;
    int n = idx / KeTOT, k = idx % KeTOT;
    int u = n >> 2, g = n & 3, col = g * HeN + u;
    float w = (k < Isz) ? Wx[k * (4 * HeN) + col] : Wh[(k - Isz) * (4 * HeN) + col];
    __nv_bfloat16 hi = __float2bfloat16(w);
    g_We_hi[n][k] = hi;
    g_We_lo[n][k] = __float2bfloat16(w - __bfloat162float(hi));
}
__global__ void conv_Wd_kernel(const float* __restrict__ Wh) {
    int idx = blockIdx.x * 256 + threadIdx.x;
    if (idx >= 4 * Hd * Hd) return;
    int n = idx / Hd, k = idx % Hd;
    int u = n >> 2, g = n & 3, col = g * Hd + u;
    float w = Wh[k * (4 * Hd) + col];
    __nv_bfloat16 hi = __float2bfloat16(w);
    g_Wd_hi[n][k] = hi;
    g_Wd_lo[n][k] = __float2bfloat16(w - __bfloat162float(hi));
}
__global__ void conv_X_kernel(const float* __restrict__ X, const float* __restrict__ Wm,
                              const float* __restrict__ A) {
    int idx = blockIdx.x * 256 + threadIdx.x;
    if (idx >= Dsz * Bsz * Isz) return;
    int t = idx / (Bsz * Isz);
    int r = idx % (Bsz * Isz);
    int m = r / Isz, k = r % Isz;
    int src = (m * Dsz + t) * Isz + k;
    float w = Wm[src];
    float v = X[src] * w + A[t * Isz + k] * (1.0f - w);
    __nv_bfloat16 hi = __float2bfloat16(v);
    g_Xe_hi[t][m][k] = hi;
    g_Xe_lo[t][m][k] = __float2bfloat16(v - __bfloat162float(hi));
}
__global__ void init_enc_kernel() {
    int i = blockIdx.x * 256 + threadIdx.x;
    if (i == 0) { g_bar_e = 0u; g_bar_d = 0u; }
    if (i >= Bsz * HeN) return;
    __nv_bfloat16 z = __float2bfloat16(0.0f);
    (&g_he_hi[0][0][0])[i] = z;
    (&g_he_lo[0][0][0])[i] = z;
}

// ---------------- small outputs (accurate math; negligible cost) ----------------
__global__ void small_kernel(const float* __restrict__ mu_c_raw,
                             const float* __restrict__ sig_lat,
                             const float* __restrict__ phi_lat,
                             float* __restrict__ out_muc,
                             float* __restrict__ out_sig,
                             float* __restrict__ out_phi) {
    int tid = threadIdx.x;
    for (int i = tid; i < 8 * Hd; i += blockDim.x) {
        out_muc[i] = mu_c_raw[i];
        float v = sig_lat[i];
        out_sig[i] = fmaxf(v, 0.0f) + log1pf(expf(-fabsf(v)));
    }
    if (tid == 0) {
        float m = -1e30f;
        for (int i = 0; i < 8; ++i) m = fmaxf(m, phi_lat[i]);
        float e[8]; float s = 0.0f;
        for (int i = 0; i < 8; ++i) { e[i] = expf(phi_lat[i] - m); s += e[i]; }
        float inv = 1.0f / s;
        for (int i = 0; i < 8; ++i) out_phi[i] = e[i] * inv;
    }
}

// ============================================================================
// Persistent encoder: grid (4, 32), 256 threads (8 warps), 1 CTA/SM.
// CTA tile M=128, N=64. Warp: rows (wid&3)*32, cols (wid>>2)*32.
// K-chunks of 64 (9 chunks: X=0, h=1..8). Swizzled 128B-row tiles.
// Weights SMEM-resident; c register-resident; single counter barrier.
// ============================================================================
__global__ void __launch_bounds__(256, 1) enc_persist(
    const float* __restrict__ bias,
    const float* __restrict__ wci, const float* __restrict__ wcf,
    const float* __restrict__ wco) {
    extern __shared__ char smem[];
    const uint32_t sb = smem_u32(smem);
    const int tid = threadIdx.x, wid = tid >> 5, lane = tid & 31;
    const int rw = wid & 3, cw = wid >> 2;
    const int bm0 = blockIdx.x * 128;
    const int n0  = blockIdx.y * 64;
    const int U0  = n0 >> 2;

    // ---- one-time: resident weight slab (9 chunks of 64 rows x 64 k, hi+lo) ----
#pragma unroll
    for (int c = 0; c < 9; ++c) {
        uint32_t wb = sb + c * E_WCH;
#pragma unroll
        for (int j = 0; j < 2; ++j) {
            int flat = tid + j * 256;       // 0..511
            int row = flat >> 3, c16 = flat & 7;
            uint32_t off = swz(row * 128 + c16 * 16);
            CP16(wb + off,        &g_We_hi[n0 + row][c * 64 + c16 * 8]);
            CP16(wb + 8192 + off, &g_We_lo[n0 + row][c * 64 + c16 * 8]);
        }
    }
    CP_COMMIT();
    // ---- one-time: gate constants to smem ----
    float* csm = (float*)(smem + E_CONST);
    if (tid < 16) {
        int u = U0 + tid;
        csm[tid]      = bias[u];
        csm[16 + tid] = bias[HeN + u];
        csm[32 + tid] = bias[2 * HeN + u];
        csm[48 + tid] = bias[3 * HeN + u];
        csm[64 + tid] = wci[u];
        csm[80 + tid] = wcf[u];
        csm[96 + tid] = wco[u];
    }
    CP_WAIT0();
    __syncthreads();

    // A-issue: 128 rows x 64 k (hi+lo), 4 iterations of 256 threads
#define E_AISSUE(ah_, al_, ap_, kb_, s_) do { \
        uint32_t so_ = sb + E_A0 + (s_) * E_AST; \
        _Pragma("unroll") \
        for (int j = 0; j < 4; ++j) { \
            int flat = tid + j * 256; \
            int row = flat >> 3, c16 = flat & 7; \
            uint32_t off = swz(row * 128 + c16 * 16); \
            CP16(so_ + off,         (ah_) + (bm0 + row) * (ap_) + (kb_) + c16 * 8); \
            CP16(so_ + 16384 + off, (al_) + (bm0 + row) * (ap_) + (kb_) + c16 * 8); \
        } \
    } while (0)

    // prefetch X chunk of step 0 into stage 0
    E_AISSUE((&g_Xe_hi[0][0][0]), (&g_Xe_lo[0][0][0]), Isz, 0, 0);
    CP_COMMIT();

    // ldmatrix per-lane address components
    const int a_row = (lane & 7) + ((lane >> 3) & 1) * 8;
    const int a_kb  = ((lane >> 4) & 1) * 16;
    const int b_row = (lane & 7) + (lane >> 4) * 8;
    const int b_kb  = ((lane >> 3) & 1) * 16;
    const uint32_t lxor = (uint32_t)((lane & 7) << 4);   // swizzle xor (row low bits)
    float* epi = (float*)(smem + E_A0);

    // register-resident cell state: thread owns (row = tid&127, units U0+uh*8..+8)
    float creg[8] = {0.f, 0.f, 0.f, 0.f, 0.f, 0.f, 0.f, 0.f};

    for (int t = 0; t < Dsz; ++t) {
        const int buf = t & 1;
        const __nv_bfloat16* __restrict__ hhi = &g_he_hi[buf][0][0];
        const __nv_bfloat16* __restrict__ hlo = &g_he_lo[buf][0][0];

        // prologue: issue h chunk 1 into stage 1
        E_AISSUE(hhi, hlo, HeN, 0, 1);
        CP_COMMIT();

        float acc[2][4][4];
#pragma unroll
        for (int mt = 0; mt < 2; ++mt)
#pragma unroll
            for (int nt = 0; nt < 4; ++nt)
#pragma unroll
                for (int r = 0; r < 4; ++r) acc[mt][nt][r] = 0.0f;

        for (int c = 0; c < 9; ++c) {
            CP_WAIT1();
            __syncthreads();
            const uint32_t so = sb + E_A0 + (c & 1) * E_AST;
            const uint32_t wb = sb + c * E_WCH;
#pragma unroll
            for (int ks = 0; ks < 4; ++ks) {
                uint32_t Ah[2][4], Al[2][4], Bh[2][4], Bl[2][4];
#pragma unroll
                for (int mt = 0; mt < 2; ++mt) {
                    uint32_t ra = so + (uint32_t)(rw * 32 + mt * 16 + a_row) * 128
                                + (((uint32_t)(ks * 32 + a_kb)) ^ lxor);
                    ldsm4(Ah[mt], ra);
                    ldsm4(Al[mt], ra + 16384);
                }
#pragma unroll
                for (int np = 0; np < 2; ++np) {
                    uint32_t rb = wb + (uint32_t)(cw * 32 + np * 16 + b_row) * 128
                                + (((uint32_t)(ks * 32 + b_kb)) ^ lxor);
                    ldsm4(Bh[np], rb);
                    ldsm4(Bl[np], rb + 8192);
                }
#pragma unroll
                for (int mt = 0; mt < 2; ++mt)
#pragma unroll
                    for (int np = 0; np < 2; ++np) {
                        mma16816(acc[mt][2 * np],     Ah[mt], Bh[np][0], Bh[np][1]);
                        mma16816(acc[mt][2 * np + 1], Ah[mt], Bh[np][2], Bh[np][3]);
                        mma16816(acc[mt][2 * np],     Ah[mt], Bl[np][0], Bl[np][1]);
                        mma16816(acc[mt][2 * np + 1], Ah[mt], Bl[np][2], Bl[np][3]);
                        mma16816(acc[mt][2 * np],     Al[mt], Bh[np][0], Bh[np][1]);
                        mma16816(acc[mt][2 * np + 1], Al[mt], Bh[np][2], Bh[np][3]);
                    }
            }
            __syncthreads();
            if (c + 2 <= 8) {
                // chunk c+2 is an h chunk: kb = (c+2-1)*64
                E_AISSUE(hhi, hlo, HeN, (c + 1) * 64, (c & 1));
            }
            CP_COMMIT();
        }
        CP_WAIT0();
        __syncthreads();

        // ---- epilogue: fragments -> smem (overlays A region) ----
#pragma unroll
        for (int mt = 0; mt < 2; ++mt)
#pragma unroll
            for (int nt = 0; nt < 4; ++nt) {
                int r0 = rw * 32 + mt * 16 + (lane >> 2);
                int c0 = cw * 32 + nt * 8 + (lane & 3) * 2;
                epi[r0 * EPITCH + c0]           = acc[mt][nt][0];
                epi[r0 * EPITCH + c0 + 1]       = acc[mt][nt][1];
                epi[(r0 + 8) * EPITCH + c0]     = acc[mt][nt][2];
                epi[(r0 + 8) * EPITCH + c0 + 1] = acc[mt][nt][3];
            }
        __syncthreads();

        // ---- pointwise: thread = (row = tid&127, unit-half = tid>>7) ----
        const int row = tid & 127;
        const int uh  = tid >> 7;
        const int grow = bm0 + row;
        alignas(16) unsigned short hh16[8], hl16[8];
#pragma unroll
        for (int j = 0; j < 8; ++j) {
            int ui = uh * 8 + j;
            float c_old = creg[j];
            float zi = epi[row * EPITCH + 4 * ui + 0] + csm[ui];
            float zf = epi[row * EPITCH + 4 * ui + 1] + csm[16 + ui];
            float zg = epi[row * EPITCH + 4 * ui + 2] + csm[32 + ui];
            float zo = epi[row * EPITCH + 4 * ui + 3] + csm[48 + ui];
            float ig = sigm(zi + c_old * csm[64 + ui]);
            float fg = sigm(zf + c_old * csm[80 + ui]);
            float cn = fg * c_old + ig * tanh_fast(zg);
            float og = sigm(zo + cn * csm[96 + ui]);
            float h  = og * tanh_fast(cn);
            creg[j] = cn;
            __nv_bfloat16 hb = __float2bfloat16(h);
            hh16[j] = __bfloat16_as_ushort(hb);
            hl16[j] = __bfloat16_as_ushort(__float2bfloat16(h - __bfloat162float(hb)));
        }
        *(uint4*)&g_he_hi[buf ^ 1][grow][U0 + uh * 8] = ((uint4*)hh16)[0];
        *(uint4*)&g_he_lo[buf ^ 1][grow][U0 + uh * 8] = ((uint4*)hl16)[0];
        __syncthreads();     // all epi reads done before stage-0 prefetch overwrites

        if (t + 1 < Dsz) {
            // prefetch next step's X chunk (independent of the barrier)
            E_AISSUE((&g_Xe_hi[t + 1][0][0]), (&g_Xe_lo[t + 1][0][0]), Isz, 0, 0);
            CP_COMMIT();

            // ---- global step barrier ----
            __threadfence();
            __syncthreads();
            if (tid == 0) {
                atomicAdd(&g_bar_e, 1u);
                unsigned int target = 128u * (unsigned int)(t + 1);
                while (*(volatile unsigned int*)&g_bar_e < target) { }
                __threadfence();
            }
            __syncthreads();
        }
    }
#undef E_AISSUE
}

// ---------------- latent z + decoder init ----------------
__global__ void z_kernel(const float* __restrict__ noise,
                         float* __restrict__ out_z,
                         float* __restrict__ out_mu,
                         float* __restrict__ out_ls) {
    int idx = blockIdx.x * blockDim.x + threadIdx.x;
    if (idx >= Bsz * Hd) return;
    int b = idx >> 8;
    int u = idx & 255;
    float mu = __bfloat162float(g_he_hi[0][b][u]) + __bfloat162float(g_he_lo[0][b][u]);
    float ls = __bfloat162float(g_he_hi[0][b][Hd + u]) + __bfloat162float(g_he_lo[0][b][Hd + u]);
    float zz = mu + expf(0.5f * ls) * noise[idx];
    out_mu[idx] = mu;
    out_ls[idx] = ls;
    out_z[idx]  = zz;
    g_c_d[idx]  = zz;
}

// ============================================================================
// Persistent decoder: grid (8, 16), 256 threads (8 warps), 1 CTA/SM.
// CTA tile M=64, N=64. Warp: rows (wid&1)*32, cols (wid>>1)*16. Inputs zero.
// K-chunks of 64 (4 chunks). Swizzled 128B tiles. c register-resident.
// ============================================================================
__global__ void __launch_bounds__(256, 1) dec_persist(
    const float* __restrict__ bias,
    const float* __restrict__ wci, const float* __restrict__ wcf,
    const float* __restrict__ wco) {
    extern __shared__ char smem[];
    const uint32_t sb = smem_u32(smem);
    const int tid = threadIdx.x, wid = tid >> 5, lane = tid & 31;
    const int rw = wid & 1, cw = wid >> 1;
    const int bm0 = blockIdx.x * 64;
    const int n0  = blockIdx.y * 64;
    const int U0  = n0 >> 2;

    // ---- one-time: resident weight slab (4 chunks) ----
#pragma unroll
    for (int c = 0; c < 4; ++c) {
        uint32_t wb = sb + c * D_WCH;
#pragma unroll
        for (int j = 0; j < 2; ++j) {
            int flat = tid + j * 256;
            int row = flat >> 3, c16 = flat & 7;
            uint32_t off = swz(row * 128 + c16 * 16);
            CP16(wb + off,        &g_Wd_hi[n0 + row][c * 64 + c16 * 8]);
            CP16(wb + 8192 + off, &g_Wd_lo[n0 + row][c * 64 + c16 * 8]);
        }
    }
    CP_COMMIT();
    float* csm = (float*)(smem + D_CONST);
    if (tid < 16) {
        int u = U0 + tid;
        csm[tid]      = bias[u];
        csm[16 + tid] = bias[Hd + u];
        csm[32 + tid] = bias[2 * Hd + u];
        csm[48 + tid] = bias[3 * Hd + u];
        csm[64 + tid] = wci[u];
        csm[80 + tid] = wcf[u];
        csm[96 + tid] = wco[u];
    }
    CP_WAIT0();
    __syncthreads();

    const int a_row = (lane & 7) + ((lane >> 3) & 1) * 8;
    const int a_kb  = ((lane >> 4) & 1) * 16;
    const int b_row = (lane & 7) + (lane >> 4) * 8;
    const int b_kb  = ((lane >> 3) & 1) * 16;
    const uint32_t lxor = (uint32_t)((lane & 7) << 4);
    float* epi = (float*)(smem + D_A0);

    // register-resident c: thread owns (row = tid&63, units U0+uq*4..+4); c0 = z
    const int prow = tid & 63;
    const int puq  = tid >> 6;
    const int pgrow = bm0 + prow;
    const int pub = puq * 4;
    float creg[4];
    {
        float4 v = *(float4*)&g_c_d[pgrow * Hd + U0 + pub];
        creg[0] = v.x; creg[1] = v.y; creg[2] = v.z; creg[3] = v.w;
    }

    for (int t = 0; t < Dsz; ++t) {
        const int buf = t & 1;
        if (t > 0) {
            const __nv_bfloat16* __restrict__ hhi = &g_hd_hi[buf][0][0];
            const __nv_bfloat16* __restrict__ hlo = &g_hd_lo[buf][0][0];

#define D_AISSUE(c, s) do { \
            uint32_t so_ = sb + D_A0 + (s) * D_AST; \
            int kb_ = (c) * 64; \
            _Pragma("unroll") \
            for (int j = 0; j < 2; ++j) { \
                int flat = tid + j * 256; \
                int row = flat >> 3, c16 = flat & 7; \
                uint32_t off = swz(row * 128 + c16 * 16); \
                CP16(so_ + off,        hhi + (bm0 + row) * Hd + kb_ + c16 * 8); \
                CP16(so_ + 8192 + off, hlo + (bm0 + row) * Hd + kb_ + c16 * 8); \
            } \
        } while (0)

            float acc[2][2][4];
#pragma unroll
            for (int mt = 0; mt < 2; ++mt)
#pragma unroll
                for (int nt = 0; nt < 2; ++nt)
#pragma unroll
                    for (int r = 0; r < 4; ++r) acc[mt][nt][r] = 0.0f;

            D_AISSUE(0, 0); CP_COMMIT();
            D_AISSUE(1, 1); CP_COMMIT();

            for (int c = 0; c < 4; ++c) {
                CP_WAIT1();
                __syncthreads();
                const uint32_t so = sb + D_A0 + (c & 1) * D_AST;
                const uint32_t wb = sb + c * D_WCH;
#pragma unroll
                for (int ks = 0; ks < 4; ++ks) {
                    uint32_t Ah[2][4], Al[2][4], Bh[4], Bl[4];
#pragma unroll
                    for (int mt = 0; mt < 2; ++mt) {
                        uint32_t ra = so + (uint32_t)(rw * 32 + mt * 16 + a_row) * 128
                                    + (((uint32_t)(ks * 32 + a_kb)) ^ lxor);
                        ldsm4(Ah[mt], ra);
                        ldsm4(Al[mt], ra + 8192);
                    }
                    uint32_t rb = wb + (uint32_t)(cw * 16 + b_row) * 128
                                + (((uint32_t)(ks * 32 + b_kb)) ^ lxor);
                    ldsm4(Bh, rb);
                    ldsm4(Bl, rb + 8192);
#pragma unroll
                    for (int mt = 0; mt < 2; ++mt) {
                        mma16816(acc[mt][0], Ah[mt], Bh[0], Bh[1]);
                        mma16816(acc[mt][1], Ah[mt], Bh[2], Bh[3]);
                        mma16816(acc[mt][0], Ah[mt], Bl[0], Bl[1]);
                        mma16816(acc[mt][1], Ah[mt], Bl[2], Bl[3]);
                        mma16816(acc[mt][0], Al[mt], Bh[0], Bh[1]);
                        mma16816(acc[mt][1], Al[mt], Bh[2], Bh[3]);
                    }
                }
                __syncthreads();
                if (c + 2 <= 3) { D_AISSUE(c + 2, c & 1); }
                CP_COMMIT();
            }
#undef D_AISSUE
            CP_WAIT0();
            __syncthreads();
#pragma unroll
            for (int mt = 0; mt < 2; ++mt)
#pragma unroll
                for (int nt = 0; nt < 2; ++nt) {
                    int r0 = rw * 32 + mt * 16 + (lane >> 2);
                    int c0 = cw * 16 + nt * 8 + (lane & 3) * 2;
                    epi[r0 * EPITCH + c0]           = acc[mt][nt][0];
                    epi[r0 * EPITCH + c0 + 1]       = acc[mt][nt][1];
                    epi[(r0 + 8) * EPITCH + c0]     = acc[mt][nt][2];
                    epi[(r0 + 8) * EPITCH + c0 + 1] = acc[mt][nt][3];
                }
            __syncthreads();
        }

        // ---- pointwise (register c) ----
        float* hsp = &g_hs[t][pgrow * Hd + U0 + pub];
        float hf[4];
        alignas(8) unsigned short hh16[4], hl16[4];
#pragma unroll
        for (int j = 0; j < 4; ++j) {
            int ui = pub + j;
            float c_old = creg[j];
            float zi = 0.f, zf = 0.f, zg = 0.f, zo = 0.f;
            if (t > 0) {
                zi = epi[prow * EPITCH + 4 * ui + 0];
                zf = epi[prow * EPITCH + 4 * ui + 1];
                zg = epi[prow * EPITCH + 4 * ui + 2];
                zo = epi[prow * EPITCH + 4 * ui + 3];
            }
            zi += csm[ui]; zf += csm[16 + ui]; zg += csm[32 + ui]; zo += csm[48 + ui];
            float ig = sigm(zi + c_old * csm[64 + ui]);
            float fg = sigm(zf + c_old * csm[80 + ui]);
            float cn = fg * c_old + ig * tanh_fast(zg);
            float og = sigm(zo + cn * csm[96 + ui]);
            float h  = og * tanh_fast(cn);
            creg[j] = cn; hf[j] = h;
            __nv_bfloat16 hb = __float2bfloat16(h);
            hh16[j] = __bfloat16_as_ushort(hb);
            hl16[j] = __bfloat16_as_ushort(__float2bfloat16(h - __bfloat162float(hb)));
        }
        *(float4*)hsp = make_float4(hf[0], hf[1], hf[2], hf[3]);
        *(uint2*)&g_hd_hi[buf ^ 1][pgrow][U0 + pub] = ((uint2*)hh16)[0];
        *(uint2*)&g_hd_lo[buf ^ 1][pgrow][U0 + pub] = ((uint2*)hl16)[0];

        if (t + 1 < Dsz) {
            // ---- global step barrier ----
            __threadfence();
            __syncthreads();
            if (tid == 0) {
                atomicAdd(&g_bar_d, 1u);
                unsigned int target = 128u * (unsigned int)(t + 1);
                while (*(volatile unsigned int*)&g_bar_d < target) { }
                __threadfence();
            }
            __syncthreads();
        }
    }
}

// ---------------- output projection: hs @ Wout + bout, sigmoid ----------------
// grid (Dsz, 8), 256 threads, 128KB dynamic smem. Block: 64 rows x 64 cols.
// Thread: 4 rows x 4 cols. Wout + h tile staged in smem.
__global__ __launch_bounds__(256) void out_kernel(
    const float* __restrict__ Wout, const float* __restrict__ bout,
    float* __restrict__ out_x, float* __restrict__ out_xraw) {
    extern __shared__ char smem[];
    float* Hs = (float*)(smem + O_HS);   // [64][256]
    float* Ws = (float*)(smem + O_WS);   // [256][64]
    const int t  = blockIdx.x;
    const int b0 = blockIdx.y * 64;
    const int tid = threadIdx.x;

    const float4* __restrict__ hsrc = (const float4*)(&g_hs[t][b0 * Hd]);
    const float4* __restrict__ wsrc = (const float4*)Wout;
#pragma unroll
    for (int j = 0; j < 16; ++j) {
        int flat = tid + j * 256;          // 0..4095 float4 slots
        ((float4*)Hs)[flat] = hsrc[flat];
        ((float4*)Ws)[flat] = wsrc[flat];
    }
    __syncthreads();

    const int cx = tid & 15;               // col group: cols cx*4..+4
    const int ry = tid >> 4;               // row group: rows ry*4..+4
    float acc[4][4];
#pragma unroll
    for (int i = 0; i < 4; ++i)
#pragma unroll
        for (int j = 0; j < 4; ++j) acc[i][j] = 0.0f;

    for (int k = 0; k < 256; ++k) {
        float4 w = *(float4*)&Ws[k * 64 + cx * 4];
#pragma unroll
        for (int i = 0; i < 4; ++i) {
            float h = Hs[(ry * 4 + i) * 256 + k];
            acc[i][0] += h * w.x;
            acc[i][1] += h * w.y;
            acc[i][2] += h * w.z;
            acc[i][3] += h * w.w;
        }
    }
    float4 bo = *(const float4*)&bout[cx * 4];
#pragma unroll
    for (int i = 0; i < 4; ++i) {
        int row = b0 + ry * 4 + i;
        int oi = (row * Dsz + t) * Isz + cx * 4;
        float4 xr = make_float4(acc[i][0] + bo.x, acc[i][1] + bo.y,
                                acc[i][2] + bo.z, acc[i][3] + bo.w);
        *(float4*)&out_xraw[oi] = xr;
        float4 xs;
        xs.x = sigm(xr.x);
        xs.y = sigm(xr.y);
        xs.z = sigm(xr.z);
        xs.w = sigm(xr.w);
        *(float4*)&out_x[oi] = xs;
    }
}

// ---------------- launch ----------------
extern "C" void kernel_launch(void* const* d_in, const int* in_sizes, int n_in,
                              void* d_out, int out_size) {
    (void)in_sizes; (void)n_in; (void)out_size;
    const float* X      = (const float*)d_in[0];
    const float* Wm     = (const float*)d_in[1];
    const float* noise  = (const float*)d_in[2];
    const float* A      = (const float*)d_in[3];
    const float* Wx_e   = (const float*)d_in[4];
    const float* Wh_e   = (const float*)d_in[5];
    const float* b_e    = (const float*)d_in[6];
    const float* wci_e  = (const float*)d_in[7];
    const float* wcf_e  = (const float*)d_in[8];
    const float* wco_e  = (const float*)d_in[9];
    // d_in[10] = Wx_d : unused (decoder inputs are zero)
    const float* Wh_d   = (const float*)d_in[11];
    const float* b_d    = (const float*)d_in[12];
    const float* wci_d  = (const float*)d_in[13];
    const float* wcf_d  = (const float*)d_in[14];
    const float* wco_d  = (const float*)d_in[15];
    const float* Wout   = (const float*)d_in[16];
    const float* bout   = (const float*)d_in[17];
    const float* mu_c_r = (const float*)d_in[18];
    const float* sig_l  = (const float*)d_in[19];
    const float* phi_l  = (const float*)d_in[20];

    float* out = (float*)d_out;
    float* out_x    = out;                 // 4194304
    float* out_xraw = out + 4194304;       // 4194304
    float* out_muc  = out + 8388608;       // 2048
    float* out_sig  = out + 8390656;       // 2048
    float* out_phi  = out + 8392704;       // 8
    float* out_z    = out + 8392712;       // 131072
    float* out_mu   = out + 8523784;       // 131072
    float* out_ls   = out + 8654856;       // 131072

    cudaFuncSetAttribute(enc_persist, cudaFuncAttributeMaxDynamicSharedMemorySize, E_SMEMP);
    cudaFuncSetAttribute(dec_persist, cudaFuncAttributeMaxDynamicSharedMemorySize, D_SMEMP);
    cudaFuncSetAttribute(out_kernel,  cudaFuncAttributeMaxDynamicSharedMemorySize, O_SMEM);

    conv_We_kernel<<<(4 * HeN * KeTOT + 255) / 256, 256>>>(Wx_e, Wh_e);
    conv_Wd_kernel<<<(4 * Hd * Hd + 255) / 256, 256>>>(Wh_d);
    conv_X_kernel<<<(Dsz * Bsz * Isz + 255) / 256, 256>>>(X, Wm, A);
    init_enc_kernel<<<(Bsz * HeN + 255) / 256, 256>>>();
    small_kernel<<<1, 256>>>(mu_c_r, sig_l, phi_l, out_muc, out_sig, out_phi);

    enc_persist<<<dim3(4, 32), 256, E_SMEMP>>>(b_e, wci_e, wcf_e, wco_e);

    z_kernel<<<(Bsz * Hd + 255) / 256, 256>>>(noise, out_z, out_mu, out_ls);

    dec_persist<<<dim3(8, 16), 256, D_SMEMP>>>(b_d, wci_d, wcf_d, wco_d);

    out_kernel<<<dim3(Dsz, 8), 256, O_SMEM>>>(Wout, bout, out_x, out_xraw);
}

// round 14
// speedup vs baseline: 1.1321x; 1.0077x over previous
#include <cuda_runtime.h>
#include <cuda_bf16.h>
#include <math.h>
#include <stdint.h>

// Problem dims (fixed by setup_inputs)
#define Bsz 512
#define Dsz 128
#define Isz 64
#define Hd  256           // decoder hidden
#define HeN 512           // encoder hidden
#define KeTOT (Isz + HeN) // 576

// ---------------- device scratch (static, no allocations) ----------------
__device__ __nv_bfloat16 g_We_hi[4 * HeN][KeTOT];  // [n'=u*4+g][k]
__device__ __nv_bfloat16 g_We_lo[4 * HeN][KeTOT];
__device__ __nv_bfloat16 g_Wd_hi[4 * Hd][Hd];
__device__ __nv_bfloat16 g_Wd_lo[4 * Hd][Hd];
__device__ __nv_bfloat16 g_Xe_hi[Dsz][Bsz][Isz];   // X_imp split, [t][m][k]
__device__ __nv_bfloat16 g_Xe_lo[Dsz][Bsz][Isz];
__device__ __nv_bfloat16 g_he_hi[2][Bsz][HeN];     // encoder h ping-pong (split)
__device__ __nv_bfloat16 g_he_lo[2][Bsz][HeN];
__device__ __nv_bfloat16 g_hd_hi[2][Bsz][Hd];      // decoder h ping-pong (split)
__device__ __nv_bfloat16 g_hd_lo[2][Bsz][Hd];
__device__ float g_c_d[Bsz * Hd];                  // decoder c0 (= z), read once
__device__ float g_hs[Dsz][Bsz * Hd];              // decoder h sequence fp32
__device__ unsigned int g_bar_e;                   // persistent-kernel step barriers
__device__ unsigned int g_bar_d;

// fast transcendentals (error ~1e-6 rel; budget is 1e-3, current rel_err 8e-6)
__device__ __forceinline__ float sigm(float x) {
    return __fdividef(1.0f, 1.0f + __expf(-x));
}
__device__ __forceinline__ float tanh_fast(float x) {
    return 1.0f - __fdividef(2.0f, __expf(2.0f * x) + 1.0f);
}

// ---------------- low-level helpers ----------------
__device__ __forceinline__ uint32_t smem_u32(const void* p) {
    uint32_t a;
    asm("{ .reg .u64 t; cvta.to.shared.u64 t, %1; cvt.u32.u64 %0, t; }" : "=r"(a) : "l"(p));
    return a;
}
#define CP16(dst, src) \
    asm volatile("cp.async.cg.shared.global [%0], [%1], 16;" :: "r"(dst), "l"(src) : "memory")
#define CP_COMMIT() asm volatile("cp.async.commit_group;" ::: "memory")
#define CP_WAIT1()  asm volatile("cp.async.wait_group 1;" ::: "memory")
#define CP_WAIT0()  asm volatile("cp.async.wait_group 0;" ::: "memory")

__device__ __forceinline__ void ldsm4(uint32_t* d, uint32_t addr) {
    asm volatile("ldmatrix.sync.aligned.m8n8.x4.shared.b16 {%0,%1,%2,%3}, [%4];"
        : "=r"(d[0]), "=r"(d[1]), "=r"(d[2]), "=r"(d[3]) : "r"(addr));
}
__device__ __forceinline__ void mma16816(float* c, const uint32_t* a, uint32_t b0, uint32_t b1) {
    asm volatile("mma.sync.aligned.m16n8k16.row.col.f32.bf16.bf16.f32 "
        "{%0,%1,%2,%3}, {%4,%5,%6,%7}, {%8,%9}, {%0,%1,%2,%3};"
        : "+f"(c[0]), "+f"(c[1]), "+f"(c[2]), "+f"(c[3])
        : "r"(a[0]), "r"(a[1]), "r"(a[2]), "r"(a[3]), "r"(b0), "r"(b1));
}

// 128B-row tiles with XOR swizzle (Swizzle<3,4,3>): bits[6:4] ^= bits[9:7]
__device__ __forceinline__ uint32_t swz(uint32_t off) { return off ^ ((off >> 3) & 0x70); }

// ---- encoder persistent layout (K-chunks of 64) ----
#define E_WCH   16384                    // weight chunk: 64 rows x 128B, hi + lo
#define E_WS_SZ (9 * E_WCH)              // 147456 B resident weights
#define E_AST   32768                    // A stage: 128 rows x 128B, hi + lo
#define E_A0    E_WS_SZ
#define E_CONST (E_A0 + 2 * E_AST)       // 212992
#define E_HST   (E_CONST + 512)          // h staging: 128x16 bf16 hi (4KB) + lo (4KB)
#define E_SMEMP (E_HST + 8192)           // 221696 B
// ---- decoder persistent layout ----
#define D_WCH   16384
#define D_WS_SZ (4 * D_WCH)              // 65536 B
#define D_AST   16384                    // 64 rows x 128B, hi + lo
#define D_A0    D_WS_SZ
#define D_CONST (D_A0 + 2 * D_AST)       // 98304
#define D_HST   (D_CONST + 512)          // hi 2KB + lo 2KB + fp32 4KB
#define D_SMEMP (D_HST + 8192)           // 107008 B
// ---- out_kernel layout: Hs 64x256 fp32 + Ws 256x64 fp32 ----
#define O_HS   0
#define O_WS   (64 * 256 * 4)            // 65536
#define O_SMEM (O_WS + 256 * 64 * 4)     // 131072

// ---------------- prep kernels ----------------
__global__ void conv_We_kernel(const float* __restrict__ Wx, const float* __restrict__ Wh) {
    int idx = blockIdx.x * 256 + threadIdx.x;
    if (idx >= 4 * HeN * KeTOT) return;
    int n = idx / KeTOT, k = idx % KeTOT;
    int u = n >> 2, g = n & 3, col = g * HeN + u;
    float w = (k < Isz) ? Wx[k * (4 * HeN) + col] : Wh[(k - Isz) * (4 * HeN) + col];
    __nv_bfloat16 hi = __float2bfloat16(w);
    g_We_hi[n][k] = hi;
    g_We_lo[n][k] = __float2bfloat16(w - __bfloat162float(hi));
}
__global__ void conv_Wd_kernel(const float* __restrict__ Wh) {
    int idx = blockIdx.x * 256 + threadIdx.x;
    if (idx >= 4 * Hd * Hd) return;
    int n = idx / Hd, k = idx % Hd;
    int u = n >> 2, g = n & 3, col = g * Hd + u;
    float w = Wh[k * (4 * Hd) + col];
    __nv_bfloat16 hi = __float2bfloat16(w);
    g_Wd_hi[n][k] = hi;
    g_Wd_lo[n][k] = __float2bfloat16(w - __bfloat162float(hi));
}
__global__ void conv_X_kernel(const float* __restrict__ X, const float* __restrict__ Wm,
                              const float* __restrict__ A) {
    int idx = blockIdx.x * 256 + threadIdx.x;
    if (idx >= Dsz * Bsz * Isz) return;
    int t = idx / (Bsz * Isz);
    int r = idx % (Bsz * Isz);
    int m = r / Isz, k = r % Isz;
    int src = (m * Dsz + t) * Isz + k;
    float w = Wm[src];
    float v = X[src] * w + A[t * Isz + k] * (1.0f - w);
    __nv_bfloat16 hi = __float2bfloat16(v);
    g_Xe_hi[t][m][k] = hi;
    g_Xe_lo[t][m][k] = __float2bfloat16(v - __bfloat162float(hi));
}
__global__ void init_enc_kernel() {
    int i = blockIdx.x * 256 + threadIdx.x;
    if (i == 0) { g_bar_e = 0u; g_bar_d = 0u; }
    if (i >= Bsz * HeN) return;
    __nv_bfloat16 z = __float2bfloat16(0.0f);
    (&g_he_hi[0][0][0])[i] = z;
    (&g_he_lo[0][0][0])[i] = z;
}

// ---------------- small outputs (accurate math; negligible cost) ----------------
__global__ void small_kernel(const float* __restrict__ mu_c_raw,
                             const float* __restrict__ sig_lat,
                             const float* __restrict__ phi_lat,
                             float* __restrict__ out_muc,
                             float* __restrict__ out_sig,
                             float* __restrict__ out_phi) {
    int tid = threadIdx.x;
    for (int i = tid; i < 8 * Hd; i += blockDim.x) {
        out_muc[i] = mu_c_raw[i];
        float v = sig_lat[i];
        out_sig[i] = fmaxf(v, 0.0f) + log1pf(expf(-fabsf(v)));
    }
    if (tid == 0) {
        float m = -1e30f;
        for (int i = 0; i < 8; ++i) m = fmaxf(m, phi_lat[i]);
        float e[8]; float s = 0.0f;
        for (int i = 0; i < 8; ++i) { e[i] = expf(phi_lat[i] - m); s += e[i]; }
        float inv = 1.0f / s;
        for (int i = 0; i < 8; ++i) out_phi[i] = e[i] * inv;
    }
}

// ============================================================================
// Persistent encoder: grid (4, 32), 256 threads (8 warps), 1 CTA/SM.
// CTA tile M=128, N=64. Warp: rows (wid&3)*32, cols (wid>>2)*32.
// K-chunks of 64 (9 chunks). Swizzled 128B tiles. Weights + consts SMEM-
// resident; c register-resident IN FRAGMENT LAYOUT; gates computed directly
// in MMA fragments via lane-pair shfl (no fp32 smem epilogue roundtrip).
// ============================================================================
__global__ void __launch_bounds__(256, 1) enc_persist(
    const float* __restrict__ bias,
    const float* __restrict__ wci, const float* __restrict__ wcf,
    const float* __restrict__ wco) {
    extern __shared__ char smem[];
    const uint32_t sb = smem_u32(smem);
    const int tid = threadIdx.x, wid = tid >> 5, lane = tid & 31;
    const int rw = wid & 3, cw = wid >> 2;
    const int bm0 = blockIdx.x * 128;
    const int n0  = blockIdx.y * 64;
    const int U0  = n0 >> 2;

    // ---- one-time: resident weight slab ----
#pragma unroll
    for (int c = 0; c < 9; ++c) {
        uint32_t wb = sb + c * E_WCH;
#pragma unroll
        for (int j = 0; j < 2; ++j) {
            int flat = tid + j * 256;
            int row = flat >> 3, c16 = flat & 7;
            uint32_t off = swz(row * 128 + c16 * 16);
            CP16(wb + off,        &g_We_hi[n0 + row][c * 64 + c16 * 8]);
            CP16(wb + 8192 + off, &g_We_lo[n0 + row][c * 64 + c16 * 8]);
        }
    }
    CP_COMMIT();
    float* csm = (float*)(smem + E_CONST);
    if (tid < 16) {
        int u = U0 + tid;
        csm[tid]      = bias[u];
        csm[16 + tid] = bias[HeN + u];
        csm[32 + tid] = bias[2 * HeN + u];
        csm[48 + tid] = bias[3 * HeN + u];
        csm[64 + tid] = wci[u];
        csm[80 + tid] = wcf[u];
        csm[96 + tid] = wco[u];
    }
    CP_WAIT0();
    __syncthreads();

#define E_AISSUE(ah_, al_, ap_, kb_, s_) do { \
        uint32_t so_ = sb + E_A0 + (s_) * E_AST; \
        _Pragma("unroll") \
        for (int j = 0; j < 4; ++j) { \
            int flat = tid + j * 256; \
            int row = flat >> 3, c16 = flat & 7; \
            uint32_t off = swz(row * 128 + c16 * 16); \
            CP16(so_ + off,         (ah_) + (bm0 + row) * (ap_) + (kb_) + c16 * 8); \
            CP16(so_ + 16384 + off, (al_) + (bm0 + row) * (ap_) + (kb_) + c16 * 8); \
        } \
    } while (0)

    // prefetch X chunk of step 0 into stage 0
    E_AISSUE((&g_Xe_hi[0][0][0]), (&g_Xe_lo[0][0][0]), Isz, 0, 0);
    CP_COMMIT();

    const int a_row = (lane & 7) + ((lane >> 3) & 1) * 8;
    const int a_kb  = ((lane >> 4) & 1) * 16;
    const int b_row = (lane & 7) + (lane >> 4) * 8;
    const int b_kb  = ((lane >> 3) & 1) * 16;
    const uint32_t lxor = (uint32_t)((lane & 7) << 4);
    const int q = lane & 3;
    const bool evn = (q & 1) == 0;
    unsigned short* hsh = (unsigned short*)(smem + E_HST);
    unsigned short* hsl = (unsigned short*)(smem + E_HST + 4096);

    // register-resident c in fragment layout: creg[mt*4+nt] for (myrow, ul)
    float creg[8] = {0.f, 0.f, 0.f, 0.f, 0.f, 0.f, 0.f, 0.f};

    for (int t = 0; t < Dsz; ++t) {
        const int buf = t & 1;
        const __nv_bfloat16* __restrict__ hhi = &g_he_hi[buf][0][0];
        const __nv_bfloat16* __restrict__ hlo = &g_he_lo[buf][0][0];

        E_AISSUE(hhi, hlo, HeN, 0, 1);   // h chunk 1 -> stage 1
        CP_COMMIT();

        float acc[2][4][4];
#pragma unroll
        for (int mt = 0; mt < 2; ++mt)
#pragma unroll
            for (int nt = 0; nt < 4; ++nt)
#pragma unroll
                for (int r = 0; r < 4; ++r) acc[mt][nt][r] = 0.0f;

        for (int c = 0; c < 9; ++c) {
            CP_WAIT1();
            __syncthreads();
            const uint32_t so = sb + E_A0 + (c & 1) * E_AST;
            const uint32_t wb = sb + c * E_WCH;
#pragma unroll
            for (int ks = 0; ks < 4; ++ks) {
                uint32_t Ah[2][4], Al[2][4], Bh[2][4], Bl[2][4];
#pragma unroll
                for (int mt = 0; mt < 2; ++mt) {
                    uint32_t ra = so + (uint32_t)(rw * 32 + mt * 16 + a_row) * 128
                                + (((uint32_t)(ks * 32 + a_kb)) ^ lxor);
                    ldsm4(Ah[mt], ra);
                    ldsm4(Al[mt], ra + 16384);
                }
#pragma unroll
                for (int np = 0; np < 2; ++np) {
                    uint32_t rb = wb + (uint32_t)(cw * 32 + np * 16 + b_row) * 128
                                + (((uint32_t)(ks * 32 + b_kb)) ^ lxor);
                    ldsm4(Bh[np], rb);
                    ldsm4(Bl[np], rb + 8192);
                }
#pragma unroll
                for (int mt = 0; mt < 2; ++mt)
#pragma unroll
                    for (int np = 0; np < 2; ++np) {
                        mma16816(acc[mt][2 * np],     Ah[mt], Bh[np][0], Bh[np][1]);
                        mma16816(acc[mt][2 * np + 1], Ah[mt], Bh[np][2], Bh[np][3]);
                        mma16816(acc[mt][2 * np],     Ah[mt], Bl[np][0], Bl[np][1]);
                        mma16816(acc[mt][2 * np + 1], Ah[mt], Bl[np][2], Bl[np][3]);
                        mma16816(acc[mt][2 * np],     Al[mt], Bh[np][0], Bh[np][1]);
                        mma16816(acc[mt][2 * np + 1], Al[mt], Bh[np][2], Bh[np][3]);
                    }
            }
            __syncthreads();
            if (c + 2 <= 8) {
                E_AISSUE(hhi, hlo, HeN, (c + 1) * 64, (c & 1));
            }
            CP_COMMIT();
        }
        CP_WAIT0();

        // ---- gates directly in fragment layout ----
#pragma unroll
        for (int mt = 0; mt < 2; ++mt)
#pragma unroll
            for (int nt = 0; nt < 4; ++nt) {
                float a0 = acc[mt][nt][0], a1 = acc[mt][nt][1];
                float a2 = acc[mt][nt][2], a3 = acc[mt][nt][3];
                float v0 = __shfl_xor_sync(0xffffffffu, evn ? a2 : a0, 1);
                float v1 = __shfl_xor_sync(0xffffffffu, evn ? a3 : a1, 1);
                float zi = evn ? a0 : v0;
                float zf = evn ? a1 : v1;
                float zg = evn ? v0 : a2;
                float zo = evn ? v1 : a3;
                int ul = cw * 8 + nt * 2 + (q >> 1);
                int myrow = rw * 32 + mt * 16 + (lane >> 2) + (evn ? 0 : 8);
                float c_old = creg[mt * 4 + nt];
                zi += csm[ul]; zf += csm[16 + ul]; zg += csm[32 + ul]; zo += csm[48 + ul];
                float ig = sigm(zi + c_old * csm[64 + ul]);
                float fg = sigm(zf + c_old * csm[80 + ul]);
                float cn = fg * c_old + ig * tanh_fast(zg);
                float og = sigm(zo + cn * csm[96 + ul]);
                float h  = og * tanh_fast(cn);
                creg[mt * 4 + nt] = cn;
                __nv_bfloat16 hb = __float2bfloat16(h);
                hsh[myrow * 16 + ul] = __bfloat16_as_ushort(hb);
                hsl[myrow * 16 + ul] = __bfloat16_as_ushort(__float2bfloat16(h - __bfloat162float(hb)));
            }
        __syncthreads();     // hstage complete; all warps done with A stages

        // ---- coalesced h copy-out: thread<128 hi rows, >=128 lo rows ----
        {
            int r = tid & 127;
            const uint4* src = (const uint4*)((tid < 128 ? (char*)hsh : (char*)hsl) + r * 32);
            uint4* dst = (tid < 128) ? (uint4*)&g_he_hi[buf ^ 1][bm0 + r][U0]
                                     : (uint4*)&g_he_lo[buf ^ 1][bm0 + r][U0];
            dst[0] = src[0];
            dst[1] = src[1];
        }

        if (t + 1 < Dsz) {
            // prefetch next step's X chunk (safe: all warps past chunk-8 reads)
            E_AISSUE((&g_Xe_hi[t + 1][0][0]), (&g_Xe_lo[t + 1][0][0]), Isz, 0, 0);
            CP_COMMIT();

            // ---- global step barrier ----
            __threadfence();
            __syncthreads();
            if (tid == 0) {
                atomicAdd(&g_bar_e, 1u);
                unsigned int target = 128u * (unsigned int)(t + 1);
                while (*(volatile unsigned int*)&g_bar_e < target) { }
                __threadfence();
            }
            __syncthreads();
        }
    }
#undef E_AISSUE
}

// ---------------- latent z + decoder init ----------------
__global__ void z_kernel(const float* __restrict__ noise,
                         float* __restrict__ out_z,
                         float* __restrict__ out_mu,
                         float* __restrict__ out_ls) {
    int idx = blockIdx.x * blockDim.x + threadIdx.x;
    if (idx >= Bsz * Hd) return;
    int b = idx >> 8;
    int u = idx & 255;
    float mu = __bfloat162float(g_he_hi[0][b][u]) + __bfloat162float(g_he_lo[0][b][u]);
    float ls = __bfloat162float(g_he_hi[0][b][Hd + u]) + __bfloat162float(g_he_lo[0][b][Hd + u]);
    float zz = mu + expf(0.5f * ls) * noise[idx];
    out_mu[idx] = mu;
    out_ls[idx] = ls;
    out_z[idx]  = zz;
    g_c_d[idx]  = zz;
}

// ============================================================================
// Persistent decoder: grid (8, 16), 256 threads (8 warps), 1 CTA/SM.
// CTA tile M=64, N=64. Warp: rows (wid&1)*32, cols (wid>>1)*16. Inputs zero.
// K-chunks of 64 (4 chunks). Fragment-layout gates; c register-resident.
// ============================================================================
__global__ void __launch_bounds__(256, 1) dec_persist(
    const float* __restrict__ bias,
    const float* __restrict__ wci, const float* __restrict__ wcf,
    const float* __restrict__ wco) {
    extern __shared__ char smem[];
    const uint32_t sb = smem_u32(smem);
    const int tid = threadIdx.x, wid = tid >> 5, lane = tid & 31;
    const int rw = wid & 1, cw = wid >> 1;
    const int bm0 = blockIdx.x * 64;
    const int n0  = blockIdx.y * 64;
    const int U0  = n0 >> 2;

    // ---- one-time: resident weight slab ----
#pragma unroll
    for (int c = 0; c < 4; ++c) {
        uint32_t wb = sb + c * D_WCH;
#pragma unroll
        for (int j = 0; j < 2; ++j) {
            int flat = tid + j * 256;
            int row = flat >> 3, c16 = flat & 7;
            uint32_t off = swz(row * 128 + c16 * 16);
            CP16(wb + off,        &g_Wd_hi[n0 + row][c * 64 + c16 * 8]);
            CP16(wb + 8192 + off, &g_Wd_lo[n0 + row][c * 64 + c16 * 8]);
        }
    }
    CP_COMMIT();
    float* csm = (float*)(smem + D_CONST);
    if (tid < 16) {
        int u = U0 + tid;
        csm[tid]      = bias[u];
        csm[16 + tid] = bias[Hd + u];
        csm[32 + tid] = bias[2 * Hd + u];
        csm[48 + tid] = bias[3 * Hd + u];
        csm[64 + tid] = wci[u];
        csm[80 + tid] = wcf[u];
        csm[96 + tid] = wco[u];
    }
    CP_WAIT0();
    __syncthreads();

    const int a_row = (lane & 7) + ((lane >> 3) & 1) * 8;
    const int a_kb  = ((lane >> 4) & 1) * 16;
    const int b_row = (lane & 7) + (lane >> 4) * 8;
    const int b_kb  = ((lane >> 3) & 1) * 16;
    const uint32_t lxor = (uint32_t)((lane & 7) << 4);
    const int q = lane & 3;
    const bool evn = (q & 1) == 0;
    unsigned short* hsh = (unsigned short*)(smem + D_HST);
    unsigned short* hsl = (unsigned short*)(smem + D_HST + 2048);
    float* hsf = (float*)(smem + D_HST + 4096);

    // register-resident c in fragment layout; c0 = z
    float creg[4];
#pragma unroll
    for (int mt = 0; mt < 2; ++mt)
#pragma unroll
        for (int nt = 0; nt < 2; ++nt) {
            int ul = cw * 4 + nt * 2 + (q >> 1);
            int myrow = rw * 32 + mt * 16 + (lane >> 2) + (evn ? 0 : 8);
            creg[mt * 2 + nt] = g_c_d[(bm0 + myrow) * Hd + U0 + ul];
        }

    for (int t = 0; t < Dsz; ++t) {
        const int buf = t & 1;
        float acc[2][2][4];
#pragma unroll
        for (int mt = 0; mt < 2; ++mt)
#pragma unroll
            for (int nt = 0; nt < 2; ++nt)
#pragma unroll
                for (int r = 0; r < 4; ++r) acc[mt][nt][r] = 0.0f;

        if (t > 0) {
            const __nv_bfloat16* __restrict__ hhi = &g_hd_hi[buf][0][0];
            const __nv_bfloat16* __restrict__ hlo = &g_hd_lo[buf][0][0];

#define D_AISSUE(c, s) do { \
            uint32_t so_ = sb + D_A0 + (s) * D_AST; \
            int kb_ = (c) * 64; \
            _Pragma("unroll") \
            for (int j = 0; j < 2; ++j) { \
                int flat = tid + j * 256; \
                int row = flat >> 3, c16 = flat & 7; \
                uint32_t off = swz(row * 128 + c16 * 16); \
                CP16(so_ + off,        hhi + (bm0 + row) * Hd + kb_ + c16 * 8); \
                CP16(so_ + 8192 + off, hlo + (bm0 + row) * Hd + kb_ + c16 * 8); \
            } \
        } while (0)

            D_AISSUE(0, 0); CP_COMMIT();
            D_AISSUE(1, 1); CP_COMMIT();

            for (int c = 0; c < 4; ++c) {
                CP_WAIT1();
                __syncthreads();
                const uint32_t so = sb + D_A0 + (c & 1) * D_AST;
                const uint32_t wb = sb + c * D_WCH;
#pragma unroll
                for (int ks = 0; ks < 4; ++ks) {
                    uint32_t Ah[2][4], Al[2][4], Bh[4], Bl[4];
#pragma unroll
                    for (int mt = 0; mt < 2; ++mt) {
                        uint32_t ra = so + (uint32_t)(rw * 32 + mt * 16 + a_row) * 128
                                    + (((uint32_t)(ks * 32 + a_kb)) ^ lxor);
                        ldsm4(Ah[mt], ra);
                        ldsm4(Al[mt], ra + 8192);
                    }
                    uint32_t rb = wb + (uint32_t)(cw * 16 + b_row) * 128
                                + (((uint32_t)(ks * 32 + b_kb)) ^ lxor);
                    ldsm4(Bh, rb);
                    ldsm4(Bl, rb + 8192);
#pragma unroll
                    for (int mt = 0; mt < 2; ++mt) {
                        mma16816(acc[mt][0], Ah[mt], Bh[0], Bh[1]);
                        mma16816(acc[mt][1], Ah[mt], Bh[2], Bh[3]);
                        mma16816(acc[mt][0], Ah[mt], Bl[0], Bl[1]);
                        mma16816(acc[mt][1], Ah[mt], Bl[2], Bl[3]);
                        mma16816(acc[mt][0], Al[mt], Bh[0], Bh[1]);
                        mma16816(acc[mt][1], Al[mt], Bh[2], Bh[3]);
                    }
                }
                __syncthreads();
                if (c + 2 <= 3) { D_AISSUE(c + 2, c & 1); }
                CP_COMMIT();
            }
#undef D_AISSUE
            CP_WAIT0();
        }

        // ---- gates in fragment layout ----
#pragma unroll
        for (int mt = 0; mt < 2; ++mt)
#pragma unroll
            for (int nt = 0; nt < 2; ++nt) {
                float a0 = acc[mt][nt][0], a1 = acc[mt][nt][1];
                float a2 = acc[mt][nt][2], a3 = acc[mt][nt][3];
                float v0 = __shfl_xor_sync(0xffffffffu, evn ? a2 : a0, 1);
                float v1 = __shfl_xor_sync(0xffffffffu, evn ? a3 : a1, 1);
                float zi = evn ? a0 : v0;
                float zf = evn ? a1 : v1;
                float zg = evn ? v0 : a2;
                float zo = evn ? v1 : a3;
                int ul = cw * 4 + nt * 2 + (q >> 1);
                int myrow = rw * 32 + mt * 16 + (lane >> 2) + (evn ? 0 : 8);
                float c_old = creg[mt * 2 + nt];
                zi += csm[ul]; zf += csm[16 + ul]; zg += csm[32 + ul]; zo += csm[48 + ul];
                float ig = sigm(zi + c_old * csm[64 + ul]);
                float fg = sigm(zf + c_old * csm[80 + ul]);
                float cn = fg * c_old + ig * tanh_fast(zg);
                float og = sigm(zo + cn * csm[96 + ul]);
                float h  = og * tanh_fast(cn);
                creg[mt * 2 + nt] = cn;
                __nv_bfloat16 hb = __float2bfloat16(h);
                hsh[myrow * 16 + ul] = __bfloat16_as_ushort(hb);
                hsl[myrow * 16 + ul] = __bfloat16_as_ushort(__float2bfloat16(h - __bfloat162float(hb)));
                hsf[myrow * 16 + ul] = h;
            }
        __syncthreads();

        // ---- coalesced copy-out ----
        if (tid < 64) {
            int r = tid;
            const uint4* src = (const uint4*)((char*)hsh + r * 32);
            uint4* dst = (uint4*)&g_hd_hi[buf ^ 1][bm0 + r][U0];
            dst[0] = src[0]; dst[1] = src[1];
        } else if (tid < 128) {
            int r = tid - 64;
            const uint4* src = (const uint4*)((char*)hsl + r * 32);
            uint4* dst = (uint4*)&g_hd_lo[buf ^ 1][bm0 + r][U0];
            dst[0] = src[0]; dst[1] = src[1];
        } else {
            int i = tid - 128;
            int r = i >> 1, hhalf = i & 1;
            const uint4* src = (const uint4*)&hsf[r * 16 + hhalf * 8];
            uint4* dst = (uint4*)&g_hs[t][(bm0 + r) * Hd + U0 + hhalf * 8];
            dst[0] = src[0]; dst[1] = src[1];
        }

        if (t + 1 < Dsz) {
            // ---- global step barrier ----
            __threadfence();
            __syncthreads();
            if (tid == 0) {
                atomicAdd(&g_bar_d, 1u);
                unsigned int target = 128u * (unsigned int)(t + 1);
                while (*(volatile unsigned int*)&g_bar_d < target) { }
                __threadfence();
            }
            __syncthreads();
        }
    }
}

// ---------------- output projection: hs @ Wout + bout, sigmoid ----------------
__global__ __launch_bounds__(256) void out_kernel(
    const float* __restrict__ Wout, const float* __restrict__ bout,
    float* __restrict__ out_x, float* __restrict__ out_xraw) {
    extern __shared__ char smem[];
    float* Hs = (float*)(smem + O_HS);   // [64][256]
    float* Ws = (float*)(smem + O_WS);   // [256][64]
    const int t  = blockIdx.x;
    const int b0 = blockIdx.y * 64;
    const int tid = threadIdx.x;

    const float4* __restrict__ hsrc = (const float4*)(&g_hs[t][b0 * Hd]);
    const float4* __restrict__ wsrc = (const float4*)Wout;
#pragma unroll
    for (int j = 0; j < 16; ++j) {
        int flat = tid + j * 256;
        ((float4*)Hs)[flat] = hsrc[flat];
        ((float4*)Ws)[flat] = wsrc[flat];
    }
    __syncthreads();

    const int cx = tid & 15;
    const int ry = tid >> 4;
    float acc[4][4];
#pragma unroll
    for (int i = 0; i < 4; ++i)
#pragma unroll
        for (int j = 0; j < 4; ++j) acc[i][j] = 0.0f;

    for (int k = 0; k < 256; ++k) {
        float4 w = *(float4*)&Ws[k * 64 + cx * 4];
#pragma unroll
        for (int i = 0; i < 4; ++i) {
            float h = Hs[(ry * 4 + i) * 256 + k];
            acc[i][0] += h * w.x;
            acc[i][1] += h * w.y;
            acc[i][2] += h * w.z;
            acc[i][3] += h * w.w;
        }
    }
    float4 bo = *(const float4*)&bout[cx * 4];
#pragma unroll
    for (int i = 0; i < 4; ++i) {
        int row = b0 + ry * 4 + i;
        int oi = (row * Dsz + t) * Isz + cx * 4;
        float4 xr = make_float4(acc[i][0] + bo.x, acc[i][1] + bo.y,
                                acc[i][2] + bo.z, acc[i][3] + bo.w);
        *(float4*)&out_xraw[oi] = xr;
        float4 xs;
        xs.x = sigm(xr.x);
        xs.y = sigm(xr.y);
        xs.z = sigm(xr.z);
        xs.w = sigm(xr.w);
        *(float4*)&out_x[oi] = xs;
    }
}

// ---------------- launch ----------------
extern "C" void kernel_launch(void* const* d_in, const int* in_sizes, int n_in,
                              void* d_out, int out_size) {
    (void)in_sizes; (void)n_in; (void)out_size;
    const float* X      = (const float*)d_in[0];
    const float* Wm     = (const float*)d_in[1];
    const float* noise  = (const float*)d_in[2];
    const float* A      = (const float*)d_in[3];
    const float* Wx_e   = (const float*)d_in[4];
    const float* Wh_e   = (const float*)d_in[5];
    const float* b_e    = (const float*)d_in[6];
    const float* wci_e  = (const float*)d_in[7];
    const float* wcf_e  = (const float*)d_in[8];
    const float* wco_e  = (const float*)d_in[9];
    // d_in[10] = Wx_d : unused (decoder inputs are zero)
    const float* Wh_d   = (const float*)d_in[11];
    const float* b_d    = (const float*)d_in[12];
    const float* wci_d  = (const float*)d_in[13];
    const float* wcf_d  = (const float*)d_in[14];
    const float* wco_d  = (const float*)d_in[15];
    const float* Wout   = (const float*)d_in[16];
    const float* bout   = (const float*)d_in[17];
    const float* mu_c_r = (const float*)d_in[18];
    const float* sig_l  = (const float*)d_in[19];
    const float* phi_l  = (const float*)d_in[20];

    float* out = (float*)d_out;
    float* out_x    = out;                 // 4194304
    float* out_xraw = out + 4194304;       // 4194304
    float* out_muc  = out + 8388608;       // 2048
    float* out_sig  = out + 8390656;       // 2048
    float* out_phi  = out + 8392704;       // 8
    float* out_z    = out + 8392712;       // 131072
    float* out_mu   = out + 8523784;       // 131072
    float* out_ls   = out + 8654856;       // 131072

    cudaFuncSetAttribute(enc_persist, cudaFuncAttributeMaxDynamicSharedMemorySize, E_SMEMP);
    cudaFuncSetAttribute(dec_persist, cudaFuncAttributeMaxDynamicSharedMemorySize, D_SMEMP);
    cudaFuncSetAttribute(out_kernel,  cudaFuncAttributeMaxDynamicSharedMemorySize, O_SMEM);

    conv_We_kernel<<<(4 * HeN * KeTOT + 255) / 256, 256>>>(Wx_e, Wh_e);
    conv_Wd_kernel<<<(4 * Hd * Hd + 255) / 256, 256>>>(Wh_d);
    conv_X_kernel<<<(Dsz * Bsz * Isz + 255) / 256, 256>>>(X, Wm, A);
    init_enc_kernel<<<(Bsz * HeN + 255) / 256, 256>>>();
    small_kernel<<<1, 256>>>(mu_c_r, sig_l, phi_l, out_muc, out_sig, out_phi);

    enc_persist<<<dim3(4, 32), 256, E_SMEMP>>>(b_e, wci_e, wcf_e, wco_e);

    z_kernel<<<(Bsz * Hd + 255) / 256, 256>>>(noise, out_z, out_mu, out_ls);

    dec_persist<<<dim3(8, 16), 256, D_SMEMP>>>(b_d, wci_d, wcf_d, wco_d);

    out_kernel<<<dim3(Dsz, 8), 256, O_SMEM>>>(Wout, bout, out_x, out_xraw);
}

// round 15
// speedup vs baseline: 1.1445x; 1.0109x over previous
#include <cuda_runtime.h>
#include <cuda_bf16.h>
#include <math.h>
#include <stdint.h>

// Problem dims (fixed by setup_inputs)
#define Bsz 512
#define Dsz 128
#define Isz 64
#define Hd  256           // decoder hidden
#define HeN 512           // encoder hidden
#define KeTOT (Isz + HeN) // 576

// ---------------- device scratch (static, no allocations) ----------------
__device__ __nv_bfloat16 g_We_hi[4 * HeN][KeTOT];  // [n'=u*4+g][k]
__device__ __nv_bfloat16 g_We_lo[4 * HeN][KeTOT];
__device__ __nv_bfloat16 g_Wd_hi[4 * Hd][Hd];
__device__ __nv_bfloat16 g_Wd_lo[4 * Hd][Hd];
__device__ __nv_bfloat16 g_Xe_hi[Dsz][Bsz][Isz];   // X_imp split, [t][m][k]
__device__ __nv_bfloat16 g_Xe_lo[Dsz][Bsz][Isz];
__device__ __nv_bfloat16 g_he_hi[2][Bsz][HeN];     // encoder h ping-pong (split)
__device__ __nv_bfloat16 g_he_lo[2][Bsz][HeN];
__device__ __nv_bfloat16 g_hd_hi[2][Bsz][Hd];      // decoder h ping-pong (split)
__device__ __nv_bfloat16 g_hd_lo[2][Bsz][Hd];
__device__ float g_c_d[Bsz * Hd];                  // decoder c0 (= z), read once
__device__ float g_hs[Dsz][Bsz * Hd];              // decoder h sequence fp32
// dependency-scoped step barriers: one counter per bm-row group (256B stride)
__device__ unsigned int g_bar_eg[4][64];           // encoder: 32 CTAs per group
__device__ unsigned int g_bar_dg[8][64];           // decoder: 16 CTAs per group

// fast transcendentals (error ~1e-6 rel; budget is 1e-3, current rel_err 8e-6)
__device__ __forceinline__ float sigm(float x) {
    return __fdividef(1.0f, 1.0f + __expf(-x));
}
__device__ __forceinline__ float tanh_fast(float x) {
    return 1.0f - __fdividef(2.0f, __expf(2.0f * x) + 1.0f);
}

// ---------------- low-level helpers ----------------
__device__ __forceinline__ uint32_t smem_u32(const void* p) {
    uint32_t a;
    asm("{ .reg .u64 t; cvta.to.shared.u64 t, %1; cvt.u32.u64 %0, t; }" : "=r"(a) : "l"(p));
    return a;
}
#define CP16(dst, src) \
    asm volatile("cp.async.cg.shared.global [%0], [%1], 16;" :: "r"(dst), "l"(src) : "memory")
#define CP_COMMIT() asm volatile("cp.async.commit_group;" ::: "memory")
#define CP_WAIT1()  asm volatile("cp.async.wait_group 1;" ::: "memory")
#define CP_WAIT0()  asm volatile("cp.async.wait_group 0;" ::: "memory")

__device__ __forceinline__ void ldsm4(uint32_t* d, uint32_t addr) {
    asm volatile("ldmatrix.sync.aligned.m8n8.x4.shared.b16 {%0,%1,%2,%3}, [%4];"
        : "=r"(d[0]), "=r"(d[1]), "=r"(d[2]), "=r"(d[3]) : "r"(addr));
}
__device__ __forceinline__ void mma16816(float* c, const uint32_t* a, uint32_t b0, uint32_t b1) {
    asm volatile("mma.sync.aligned.m16n8k16.row.col.f32.bf16.bf16.f32 "
        "{%0,%1,%2,%3}, {%4,%5,%6,%7}, {%8,%9}, {%0,%1,%2,%3};"
        : "+f"(c[0]), "+f"(c[1]), "+f"(c[2]), "+f"(c[3])
        : "r"(a[0]), "r"(a[1]), "r"(a[2]), "r"(a[3]), "r"(b0), "r"(b1));
}

// 128B-row tiles with XOR swizzle (Swizzle<3,4,3>): bits[6:4] ^= bits[9:7]
__device__ __forceinline__ uint32_t swz(uint32_t off) { return off ^ ((off >> 3) & 0x70); }

// ---- encoder persistent layout (K-chunks of 64) ----
#define E_WCH   16384                    // weight chunk: 64 rows x 128B, hi + lo
#define E_WS_SZ (9 * E_WCH)              // 147456 B resident weights
#define E_AST   32768                    // A stage: 128 rows x 128B, hi + lo
#define E_A0    E_WS_SZ
#define E_CONST (E_A0 + 2 * E_AST)       // 212992
#define E_HST   (E_CONST + 512)          // h staging: 128x16 bf16 hi (4KB) + lo (4KB)
#define E_SMEMP (E_HST + 8192)           // 221696 B
// ---- decoder persistent layout ----
#define D_WCH   16384
#define D_WS_SZ (4 * D_WCH)              // 65536 B
#define D_AST   16384                    // 64 rows x 128B, hi + lo
#define D_A0    D_WS_SZ
#define D_CONST (D_A0 + 2 * D_AST)       // 98304
#define D_HST   (D_CONST + 512)          // hi 2KB + lo 2KB + fp32 4KB
#define D_SMEMP (D_HST + 8192)           // 107008 B
// ---- out_kernel layout: Hs 64x256 fp32 + Ws 256x64 fp32 ----
#define O_HS   0
#define O_WS   (64 * 256 * 4)            // 65536
#define O_SMEM (O_WS + 256 * 64 * 4)     // 131072

// ---------------- prep kernels ----------------
__global__ void conv_We_kernel(const float* __restrict__ Wx, const float* __restrict__ Wh) {
    int idx = blockIdx.x * 256 + threadIdx.x;
    if (idx >= 4 * HeN * KeTOT) return;
    int n = idx / KeTOT, k = idx % KeTOT;
    int u = n >> 2, g = n & 3, col = g * HeN + u;
    float w = (k < Isz) ? Wx[k * (4 * HeN) + col] : Wh[(k - Isz) * (4 * HeN) + col];
    __nv_bfloat16 hi = __float2bfloat16(w);
    g_We_hi[n][k] = hi;
    g_We_lo[n][k] = __float2bfloat16(w - __bfloat162float(hi));
}
__global__ void conv_Wd_kernel(const float* __restrict__ Wh) {
    int idx = blockIdx.x * 256 + threadIdx.x;
    if (idx >= 4 * Hd * Hd) return;
    int n = idx / Hd, k = idx % Hd;
    int u = n >> 2, g = n & 3, col = g * Hd + u;
    float w = Wh[k * (4 * Hd) + col];
    __nv_bfloat16 hi = __float2bfloat16(w);
    g_Wd_hi[n][k] = hi;
    g_Wd_lo[n][k] = __float2bfloat16(w - __bfloat162float(hi));
}
__global__ void conv_X_kernel(const float* __restrict__ X, const float* __restrict__ Wm,
                              const float* __restrict__ A) {
    int idx = blockIdx.x * 256 + threadIdx.x;
    if (idx >= Dsz * Bsz * Isz) return;
    int t = idx / (Bsz * Isz);
    int r = idx % (Bsz * Isz);
    int m = r / Isz, k = r % Isz;
    int src = (m * Dsz + t) * Isz + k;
    float w = Wm[src];
    float v = X[src] * w + A[t * Isz + k] * (1.0f - w);
    __nv_bfloat16 hi = __float2bfloat16(v);
    g_Xe_hi[t][m][k] = hi;
    g_Xe_lo[t][m][k] = __float2bfloat16(v - __bfloat162float(hi));
}
__global__ void init_enc_kernel() {
    int i = blockIdx.x * 256 + threadIdx.x;
    if (i < 4) g_bar_eg[i][0] = 0u;
    if (i < 8) g_bar_dg[i][0] = 0u;
    if (i >= Bsz * HeN) return;
    __nv_bfloat16 z = __float2bfloat16(0.0f);
    (&g_he_hi[0][0][0])[i] = z;
    (&g_he_lo[0][0][0])[i] = z;
}

// ---------------- small outputs (accurate math; negligible cost) ----------------
__global__ void small_kernel(const float* __restrict__ mu_c_raw,
                             const float* __restrict__ sig_lat,
                             const float* __restrict__ phi_lat,
                             float* __restrict__ out_muc,
                             float* __restrict__ out_sig,
                             float* __restrict__ out_phi) {
    int tid = threadIdx.x;
    for (int i = tid; i < 8 * Hd; i += blockDim.x) {
        out_muc[i] = mu_c_raw[i];
        float v = sig_lat[i];
        out_sig[i] = fmaxf(v, 0.0f) + log1pf(expf(-fabsf(v)));
    }
    if (tid == 0) {
        float m = -1e30f;
        for (int i = 0; i < 8; ++i) m = fmaxf(m, phi_lat[i]);
        float e[8]; float s = 0.0f;
        for (int i = 0; i < 8; ++i) { e[i] = expf(phi_lat[i] - m); s += e[i]; }
        float inv = 1.0f / s;
        for (int i = 0; i < 8; ++i) out_phi[i] = e[i] * inv;
    }
}

// ============================================================================
// Persistent encoder: grid (4, 32), 256 threads (8 warps), 1 CTA/SM.
// CTA tile M=128, N=64. Warp: rows (wid&3)*32, cols (wid>>2)*32.
// K-chunks of 64 (9 chunks). Swizzled 128B tiles. Weights + consts SMEM-
// resident; c register-resident in fragment layout; fragment-layout gates.
// Step barrier: per-bm-group counter (32 CTAs per group, 4 groups).
// ============================================================================
__global__ void __launch_bounds__(256, 1) enc_persist(
    const float* __restrict__ bias,
    const float* __restrict__ wci, const float* __restrict__ wcf,
    const float* __restrict__ wco) {
    extern __shared__ char smem[];
    const uint32_t sb = smem_u32(smem);
    const int tid = threadIdx.x, wid = tid >> 5, lane = tid & 31;
    const int rw = wid & 3, cw = wid >> 2;
    const int bm0 = blockIdx.x * 128;
    const int n0  = blockIdx.y * 64;
    const int U0  = n0 >> 2;
    unsigned int* mybar = &g_bar_eg[blockIdx.x][0];

    // ---- one-time: resident weight slab ----
#pragma unroll
    for (int c = 0; c < 9; ++c) {
        uint32_t wb = sb + c * E_WCH;
#pragma unroll
        for (int j = 0; j < 2; ++j) {
            int flat = tid + j * 256;
            int row = flat >> 3, c16 = flat & 7;
            uint32_t off = swz(row * 128 + c16 * 16);
            CP16(wb + off,        &g_We_hi[n0 + row][c * 64 + c16 * 8]);
            CP16(wb + 8192 + off, &g_We_lo[n0 + row][c * 64 + c16 * 8]);
        }
    }
    CP_COMMIT();
    float* csm = (float*)(smem + E_CONST);
    if (tid < 16) {
        int u = U0 + tid;
        csm[tid]      = bias[u];
        csm[16 + tid] = bias[HeN + u];
        csm[32 + tid] = bias[2 * HeN + u];
        csm[48 + tid] = bias[3 * HeN + u];
        csm[64 + tid] = wci[u];
        csm[80 + tid] = wcf[u];
        csm[96 + tid] = wco[u];
    }
    CP_WAIT0();
    __syncthreads();

#define E_AISSUE(ah_, al_, ap_, kb_, s_) do { \
        uint32_t so_ = sb + E_A0 + (s_) * E_AST; \
        _Pragma("unroll") \
        for (int j = 0; j < 4; ++j) { \
            int flat = tid + j * 256; \
            int row = flat >> 3, c16 = flat & 7; \
            uint32_t off = swz(row * 128 + c16 * 16); \
            CP16(so_ + off,         (ah_) + (bm0 + row) * (ap_) + (kb_) + c16 * 8); \
            CP16(so_ + 16384 + off, (al_) + (bm0 + row) * (ap_) + (kb_) + c16 * 8); \
        } \
    } while (0)

    // prefetch X chunk of step 0 into stage 0
    E_AISSUE((&g_Xe_hi[0][0][0]), (&g_Xe_lo[0][0][0]), Isz, 0, 0);
    CP_COMMIT();

    const int a_row = (lane & 7) + ((lane >> 3) & 1) * 8;
    const int a_kb  = ((lane >> 4) & 1) * 16;
    const int b_row = (lane & 7) + (lane >> 4) * 8;
    const int b_kb  = ((lane >> 3) & 1) * 16;
    const uint32_t lxor = (uint32_t)((lane & 7) << 4);
    const int q = lane & 3;
    const bool evn = (q & 1) == 0;
    unsigned short* hsh = (unsigned short*)(smem + E_HST);
    unsigned short* hsl = (unsigned short*)(smem + E_HST + 4096);

    // register-resident c in fragment layout: creg[mt*4+nt] for (myrow, ul)
    float creg[8] = {0.f, 0.f, 0.f, 0.f, 0.f, 0.f, 0.f, 0.f};

    for (int t = 0; t < Dsz; ++t) {
        const int buf = t & 1;
        const __nv_bfloat16* __restrict__ hhi = &g_he_hi[buf][0][0];
        const __nv_bfloat16* __restrict__ hlo = &g_he_lo[buf][0][0];

        E_AISSUE(hhi, hlo, HeN, 0, 1);   // h chunk 1 -> stage 1
        CP_COMMIT();

        float acc[2][4][4];
#pragma unroll
        for (int mt = 0; mt < 2; ++mt)
#pragma unroll
            for (int nt = 0; nt < 4; ++nt)
#pragma unroll
                for (int r = 0; r < 4; ++r) acc[mt][nt][r] = 0.0f;

        for (int c = 0; c < 9; ++c) {
            CP_WAIT1();
            __syncthreads();
            const uint32_t so = sb + E_A0 + (c & 1) * E_AST;
            const uint32_t wb = sb + c * E_WCH;
#pragma unroll
            for (int ks = 0; ks < 4; ++ks) {
                uint32_t Ah[2][4], Al[2][4], Bh[2][4], Bl[2][4];
#pragma unroll
                for (int mt = 0; mt < 2; ++mt) {
                    uint32_t ra = so + (uint32_t)(rw * 32 + mt * 16 + a_row) * 128
                                + (((uint32_t)(ks * 32 + a_kb)) ^ lxor);
                    ldsm4(Ah[mt], ra);
                    ldsm4(Al[mt], ra + 16384);
                }
#pragma unroll
                for (int np = 0; np < 2; ++np) {
                    uint32_t rb = wb + (uint32_t)(cw * 32 + np * 16 + b_row) * 128
                                + (((uint32_t)(ks * 32 + b_kb)) ^ lxor);
                    ldsm4(Bh[np], rb);
                    ldsm4(Bl[np], rb + 8192);
                }
#pragma unroll
                for (int mt = 0; mt < 2; ++mt)
#pragma unroll
                    for (int np = 0; np < 2; ++np) {
                        mma16816(acc[mt][2 * np],     Ah[mt], Bh[np][0], Bh[np][1]);
                        mma16816(acc[mt][2 * np + 1], Ah[mt], Bh[np][2], Bh[np][3]);
                        mma16816(acc[mt][2 * np],     Ah[mt], Bl[np][0], Bl[np][1]);
                        mma16816(acc[mt][2 * np + 1], Ah[mt], Bl[np][2], Bl[np][3]);
                        mma16816(acc[mt][2 * np],     Al[mt], Bh[np][0], Bh[np][1]);
                        mma16816(acc[mt][2 * np + 1], Al[mt], Bh[np][2], Bh[np][3]);
                    }
            }
            __syncthreads();
            if (c + 2 <= 8) {
                E_AISSUE(hhi, hlo, HeN, (c + 1) * 64, (c & 1));
            }
            CP_COMMIT();
        }
        CP_WAIT0();

        // ---- gates directly in fragment layout ----
#pragma unroll
        for (int mt = 0; mt < 2; ++mt)
#pragma unroll
            for (int nt = 0; nt < 4; ++nt) {
                float a0 = acc[mt][nt][0], a1 = acc[mt][nt][1];
                float a2 = acc[mt][nt][2], a3 = acc[mt][nt][3];
                float v0 = __shfl_xor_sync(0xffffffffu, evn ? a2 : a0, 1);
                float v1 = __shfl_xor_sync(0xffffffffu, evn ? a3 : a1, 1);
                float zi = evn ? a0 : v0;
                float zf = evn ? a1 : v1;
                float zg = evn ? v0 : a2;
                float zo = evn ? v1 : a3;
                int ul = cw * 8 + nt * 2 + (q >> 1);
                int myrow = rw * 32 + mt * 16 + (lane >> 2) + (evn ? 0 : 8);
                float c_old = creg[mt * 4 + nt];
                zi += csm[ul]; zf += csm[16 + ul]; zg += csm[32 + ul]; zo += csm[48 + ul];
                float ig = sigm(zi + c_old * csm[64 + ul]);
                float fg = sigm(zf + c_old * csm[80 + ul]);
                float cn = fg * c_old + ig * tanh_fast(zg);
                float og = sigm(zo + cn * csm[96 + ul]);
                float h  = og * tanh_fast(cn);
                creg[mt * 4 + nt] = cn;
                __nv_bfloat16 hb = __float2bfloat16(h);
                hsh[myrow * 16 + ul] = __bfloat16_as_ushort(hb);
                hsl[myrow * 16 + ul] = __bfloat16_as_ushort(__float2bfloat16(h - __bfloat162float(hb)));
            }
        __syncthreads();     // hstage complete; all warps done with A stages

        // ---- coalesced h copy-out: thread<128 hi rows, >=128 lo rows ----
        {
            int r = tid & 127;
            const uint4* src = (const uint4*)((tid < 128 ? (char*)hsh : (char*)hsl) + r * 32);
            uint4* dst = (tid < 128) ? (uint4*)&g_he_hi[buf ^ 1][bm0 + r][U0]
                                     : (uint4*)&g_he_lo[buf ^ 1][bm0 + r][U0];
            dst[0] = src[0];
            dst[1] = src[1];
        }

        if (t + 1 < Dsz) {
            // prefetch next step's X chunk (safe: all warps past chunk-8 reads)
            E_AISSUE((&g_Xe_hi[t + 1][0][0]), (&g_Xe_lo[t + 1][0][0]), Isz, 0, 0);
            CP_COMMIT();

            // ---- group step barrier (32 CTAs sharing this bm block) ----
            __threadfence();
            __syncthreads();
            if (tid == 0) {
                atomicAdd(mybar, 1u);
                unsigned int target = 32u * (unsigned int)(t + 1);
                while (*(volatile unsigned int*)mybar < target) { }
                __threadfence();
            }
            __syncthreads();
        }
    }
#undef E_AISSUE
}

// ---------------- latent z + decoder init ----------------
__global__ void z_kernel(const float* __restrict__ noise,
                         float* __restrict__ out_z,
                         float* __restrict__ out_mu,
                         float* __restrict__ out_ls) {
    int idx = blockIdx.x * blockDim.x + threadIdx.x;
    if (idx >= Bsz * Hd) return;
    int b = idx >> 8;
    int u = idx & 255;
    float mu = __bfloat162float(g_he_hi[0][b][u]) + __bfloat162float(g_he_lo[0][b][u]);
    float ls = __bfloat162float(g_he_hi[0][b][Hd + u]) + __bfloat162float(g_he_lo[0][b][Hd + u]);
    float zz = mu + expf(0.5f * ls) * noise[idx];
    out_mu[idx] = mu;
    out_ls[idx] = ls;
    out_z[idx]  = zz;
    g_c_d[idx]  = zz;
}

// ============================================================================
// Persistent decoder: grid (8, 16), 256 threads (8 warps), 1 CTA/SM.
// CTA tile M=64, N=64. Warp: rows (wid&1)*32, cols (wid>>1)*16. Inputs zero.
// K-chunks of 64 (4 chunks). Fragment-layout gates; c register-resident.
// Step barrier: per-bm-group counter (16 CTAs per group, 8 groups).
// ============================================================================
__global__ void __launch_bounds__(256, 1) dec_persist(
    const float* __restrict__ bias,
    const float* __restrict__ wci, const float* __restrict__ wcf,
    const float* __restrict__ wco) {
    extern __shared__ char smem[];
    const uint32_t sb = smem_u32(smem);
    const int tid = threadIdx.x, wid = tid >> 5, lane = tid & 31;
    const int rw = wid & 1, cw = wid >> 1;
    const int bm0 = blockIdx.x * 64;
    const int n0  = blockIdx.y * 64;
    const int U0  = n0 >> 2;
    unsigned int* mybar = &g_bar_dg[blockIdx.x][0];

    // ---- one-time: resident weight slab ----
#pragma unroll
    for (int c = 0; c < 4; ++c) {
        uint32_t wb = sb + c * D_WCH;
#pragma unroll
        for (int j = 0; j < 2; ++j) {
            int flat = tid + j * 256;
            int row = flat >> 3, c16 = flat & 7;
            uint32_t off = swz(row * 128 + c16 * 16);
            CP16(wb + off,        &g_Wd_hi[n0 + row][c * 64 + c16 * 8]);
            CP16(wb + 8192 + off, &g_Wd_lo[n0 + row][c * 64 + c16 * 8]);
        }
    }
    CP_COMMIT();
    float* csm = (float*)(smem + D_CONST);
    if (tid < 16) {
        int u = U0 + tid;
        csm[tid]      = bias[u];
        csm[16 + tid] = bias[Hd + u];
        csm[32 + tid] = bias[2 * Hd + u];
        csm[48 + tid] = bias[3 * Hd + u];
        csm[64 + tid] = wci[u];
        csm[80 + tid] = wcf[u];
        csm[96 + tid] = wco[u];
    }
    CP_WAIT0();
    __syncthreads();

    const int a_row = (lane & 7) + ((lane >> 3) & 1) * 8;
    const int a_kb  = ((lane >> 4) & 1) * 16;
    const int b_row = (lane & 7) + (lane >> 4) * 8;
    const int b_kb  = ((lane >> 3) & 1) * 16;
    const uint32_t lxor = (uint32_t)((lane & 7) << 4);
    const int q = lane & 3;
    const bool evn = (q & 1) == 0;
    unsigned short* hsh = (unsigned short*)(smem + D_HST);
    unsigned short* hsl = (unsigned short*)(smem + D_HST + 2048);
    float* hsf = (float*)(smem + D_HST + 4096);

    // register-resident c in fragment layout; c0 = z
    float creg[4];
#pragma unroll
    for (int mt = 0; mt < 2; ++mt)
#pragma unroll
        for (int nt = 0; nt < 2; ++nt) {
            int ul = cw * 4 + nt * 2 + (q >> 1);
            int myrow = rw * 32 + mt * 16 + (lane >> 2) + (evn ? 0 : 8);
            creg[mt * 2 + nt] = g_c_d[(bm0 + myrow) * Hd + U0 + ul];
        }

    for (int t = 0; t < Dsz; ++t) {
        const int buf = t & 1;
        float acc[2][2][4];
#pragma unroll
        for (int mt = 0; mt < 2; ++mt)
#pragma unroll
            for (int nt = 0; nt < 2; ++nt)
#pragma unroll
                for (int r = 0; r < 4; ++r) acc[mt][nt][r] = 0.0f;

        if (t > 0) {
            const __nv_bfloat16* __restrict__ hhi = &g_hd_hi[buf][0][0];
            const __nv_bfloat16* __restrict__ hlo = &g_hd_lo[buf][0][0];

#define D_AISSUE(c, s) do { \
            uint32_t so_ = sb + D_A0 + (s) * D_AST; \
            int kb_ = (c) * 64; \
            _Pragma("unroll") \
            for (int j = 0; j < 2; ++j) { \
                int flat = tid + j * 256; \
                int row = flat >> 3, c16 = flat & 7; \
                uint32_t off = swz(row * 128 + c16 * 16); \
                CP16(so_ + off,        hhi + (bm0 + row) * Hd + kb_ + c16 * 8); \
                CP16(so_ + 8192 + off, hlo + (bm0 + row) * Hd + kb_ + c16 * 8); \
            } \
        } while (0)

            D_AISSUE(0, 0); CP_COMMIT();
            D_AISSUE(1, 1); CP_COMMIT();

            for (int c = 0; c < 4; ++c) {
                CP_WAIT1();
                __syncthreads();
                const uint32_t so = sb + D_A0 + (c & 1) * D_AST;
                const uint32_t wb = sb + c * D_WCH;
#pragma unroll
                for (int ks = 0; ks < 4; ++ks) {
                    uint32_t Ah[2][4], Al[2][4], Bh[4], Bl[4];
#pragma unroll
                    for (int mt = 0; mt < 2; ++mt) {
                        uint32_t ra = so + (uint32_t)(rw * 32 + mt * 16 + a_row) * 128
                                    + (((uint32_t)(ks * 32 + a_kb)) ^ lxor);
                        ldsm4(Ah[mt], ra);
                        ldsm4(Al[mt], ra + 8192);
                    }
                    uint32_t rb = wb + (uint32_t)(cw * 16 + b_row) * 128
                                + (((uint32_t)(ks * 32 + b_kb)) ^ lxor);
                    ldsm4(Bh, rb);
                    ldsm4(Bl, rb + 8192);
#pragma unroll
                    for (int mt = 0; mt < 2; ++mt) {
                        mma16816(acc[mt][0], Ah[mt], Bh[0], Bh[1]);
                        mma16816(acc[mt][1], Ah[mt], Bh[2], Bh[3]);
                        mma16816(acc[mt][0], Ah[mt], Bl[0], Bl[1]);
                        mma16816(acc[mt][1], Ah[mt], Bl[2], Bl[3]);
                        mma16816(acc[mt][0], Al[mt], Bh[0], Bh[1]);
                        mma16816(acc[mt][1], Al[mt], Bh[2], Bh[3]);
                    }
                }
                __syncthreads();
                if (c + 2 <= 3) { D_AISSUE(c + 2, c & 1); }
                CP_COMMIT();
            }
#undef D_AISSUE
            CP_WAIT0();
        }

        // ---- gates in fragment layout ----
#pragma unroll
        for (int mt = 0; mt < 2; ++mt)
#pragma unroll
            for (int nt = 0; nt < 2; ++nt) {
                float a0 = acc[mt][nt][0], a1 = acc[mt][nt][1];
                float a2 = acc[mt][nt][2], a3 = acc[mt][nt][3];
                float v0 = __shfl_xor_sync(0xffffffffu, evn ? a2 : a0, 1);
                float v1 = __shfl_xor_sync(0xffffffffu, evn ? a3 : a1, 1);
                float zi = evn ? a0 : v0;
                float zf = evn ? a1 : v1;
                float zg = evn ? v0 : a2;
                float zo = evn ? v1 : a3;
                int ul = cw * 4 + nt * 2 + (q >> 1);
                int myrow = rw * 32 + mt * 16 + (lane >> 2) + (evn ? 0 : 8);
                float c_old = creg[mt * 2 + nt];
                zi += csm[ul]; zf += csm[16 + ul]; zg += csm[32 + ul]; zo += csm[48 + ul];
                float ig = sigm(zi + c_old * csm[64 + ul]);
                float fg = sigm(zf + c_old * csm[80 + ul]);
                float cn = fg * c_old + ig * tanh_fast(zg);
                float og = sigm(zo + cn * csm[96 + ul]);
                float h  = og * tanh_fast(cn);
                creg[mt * 2 + nt] = cn;
                __nv_bfloat16 hb = __float2bfloat16(h);
                hsh[myrow * 16 + ul] = __bfloat16_as_ushort(hb);
                hsl[myrow * 16 + ul] = __bfloat16_as_ushort(__float2bfloat16(h - __bfloat162float(hb)));
                hsf[myrow * 16 + ul] = h;
            }
        __syncthreads();

        // ---- coalesced copy-out ----
        if (tid < 64) {
            int r = tid;
            const uint4* src = (const uint4*)((char*)hsh + r * 32);
            uint4* dst = (uint4*)&g_hd_hi[buf ^ 1][bm0 + r][U0];
            dst[0] = src[0]; dst[1] = src[1];
        } else if (tid < 128) {
            int r = tid - 64;
            const uint4* src = (const uint4*)((char*)hsl + r * 32);
            uint4* dst = (uint4*)&g_hd_lo[buf ^ 1][bm0 + r][U0];
            dst[0] = src[0]; dst[1] = src[1];
        } else {
            int i = tid - 128;
            int r = i >> 1, hhalf = i & 1;
            const uint4* src = (const uint4*)&hsf[r * 16 + hhalf * 8];
            uint4* dst = (uint4*)&g_hs[t][(bm0 + r) * Hd + U0 + hhalf * 8];
            dst[0] = src[0]; dst[1] = src[1];
        }

        if (t + 1 < Dsz) {
            // ---- group step barrier (16 CTAs sharing this bm block) ----
            __threadfence();
            __syncthreads();
            if (tid == 0) {
                atomicAdd(mybar, 1u);
                unsigned int target = 16u * (unsigned int)(t + 1);
                while (*(volatile unsigned int*)mybar < target) { }
                __threadfence();
            }
            __syncthreads();
        }
    }
}

// ---------------- output projection: hs @ Wout + bout, sigmoid ----------------
__global__ __launch_bounds__(256) void out_kernel(
    const float* __restrict__ Wout, const float* __restrict__ bout,
    float* __restrict__ out_x, float* __restrict__ out_xraw) {
    extern __shared__ char smem[];
    float* Hs = (float*)(smem + O_HS);   // [64][256]
    float* Ws = (float*)(smem + O_WS);   // [256][64]
    const int t  = blockIdx.x;
    const int b0 = blockIdx.y * 64;
    const int tid = threadIdx.x;

    const float4* __restrict__ hsrc = (const float4*)(&g_hs[t][b0 * Hd]);
    const float4* __restrict__ wsrc = (const float4*)Wout;
#pragma unroll
    for (int j = 0; j < 16; ++j) {
        int flat = tid + j * 256;
        ((float4*)Hs)[flat] = hsrc[flat];
        ((float4*)Ws)[flat] = wsrc[flat];
    }
    __syncthreads();

    const int cx = tid & 15;
    const int ry = tid >> 4;
    float acc[4][4];
#pragma unroll
    for (int i = 0; i < 4; ++i)
#pragma unroll
        for (int j = 0; j < 4; ++j) acc[i][j] = 0.0f;

    for (int k = 0; k < 256; ++k) {
        float4 w = *(float4*)&Ws[k * 64 + cx * 4];
#pragma unroll
        for (int i = 0; i < 4; ++i) {
            float h = Hs[(ry * 4 + i) * 256 + k];
            acc[i][0] += h * w.x;
            acc[i][1] += h * w.y;
            acc[i][2] += h * w.z;
            acc[i][3] += h * w.w;
        }
    }
    float4 bo = *(const float4*)&bout[cx * 4];
#pragma unroll
    for (int i = 0; i < 4; ++i) {
        int row = b0 + ry * 4 + i;
        int oi = (row * Dsz + t) * Isz + cx * 4;
        float4 xr = make_float4(acc[i][0] + bo.x, acc[i][1] + bo.y,
                                acc[i][2] + bo.z, acc[i][3] + bo.w);
        *(float4*)&out_xraw[oi] = xr;
        float4 xs;
        xs.x = sigm(xr.x);
        xs.y = sigm(xr.y);
        xs.z = sigm(xr.z);
        xs.w = sigm(xr.w);
        *(float4*)&out_x[oi] = xs;
    }
}

// ---------------- launch ----------------
extern "C" void kernel_launch(void* const* d_in, const int* in_sizes, int n_in,
                              void* d_out, int out_size) {
    (void)in_sizes; (void)n_in; (void)out_size;
    const float* X      = (const float*)d_in[0];
    const float* Wm     = (const float*)d_in[1];
    const float* noise  = (const float*)d_in[2];
    const float* A      = (const float*)d_in[3];
    const float* Wx_e   = (const float*)d_in[4];
    const float* Wh_e   = (const float*)d_in[5];
    const float* b_e    = (const float*)d_in[6];
    const float* wci_e  = (const float*)d_in[7];
    const float* wcf_e  = (const float*)d_in[8];
    const float* wco_e  = (const float*)d_in[9];
    // d_in[10] = Wx_d : unused (decoder inputs are zero)
    const float* Wh_d   = (const float*)d_in[11];
    const float* b_d    = (const float*)d_in[12];
    const float* wci_d  = (const float*)d_in[13];
    const float* wcf_d  = (const float*)d_in[14];
    const float* wco_d  = (const float*)d_in[15];
    const float* Wout   = (const float*)d_in[16];
    const float* bout   = (const float*)d_in[17];
    const float* mu_c_r = (const float*)d_in[18];
    const float* sig_l  = (const float*)d_in[19];
    const float* phi_l  = (const float*)d_in[20];

    float* out = (float*)d_out;
    float* out_x    = out;                 // 4194304
    float* out_xraw = out + 4194304;       // 4194304
    float* out_muc  = out + 8388608;       // 2048
    float* out_sig  = out + 8390656;       // 2048
    float* out_phi  = out + 8392704;       // 8
    float* out_z    = out + 8392712;       // 131072
    float* out_mu   = out + 8523784;       // 131072
    float* out_ls   = out + 8654856;       // 131072

    cudaFuncSetAttribute(enc_persist, cudaFuncAttributeMaxDynamicSharedMemorySize, E_SMEMP);
    cudaFuncSetAttribute(dec_persist, cudaFuncAttributeMaxDynamicSharedMemorySize, D_SMEMP);
    cudaFuncSetAttribute(out_kernel,  cudaFuncAttributeMaxDynamicSharedMemorySize, O_SMEM);

    conv_We_kernel<<<(4 * HeN * KeTOT + 255) / 256, 256>>>(Wx_e, Wh_e);
    conv_Wd_kernel<<<(4 * Hd * Hd + 255) / 256, 256>>>(Wh_d);
    conv_X_kernel<<<(Dsz * Bsz * Isz + 255) / 256, 256>>>(X, Wm, A);
    init_enc_kernel<<<(Bsz * HeN + 255) / 256, 256>>>();
    small_kernel<<<1, 256>>>(mu_c_r, sig_l, phi_l, out_muc, out_sig, out_phi);

    enc_persist<<<dim3(4, 32), 256, E_SMEMP>>>(b_e, wci_e, wcf_e, wco_e);

    z_kernel<<<(Bsz * Hd + 255) / 256, 256>>>(noise, out_z, out_mu, out_ls);

    dec_persist<<<dim3(8, 16), 256, D_SMEMP>>>(b_d, wci_d, wcf_d, wco_d);

    out_kernel<<<dim3(Dsz, 8), 256, O_SMEM>>>(Wout, bout, out_x, out_xraw);
}

// round 16
// speedup vs baseline: 1.1846x; 1.0350x over previous
#include <cuda_runtime.h>
#include <cuda_bf16.h>
#include <math.h>
#include <stdint.h>

// Problem dims (fixed by setup_inputs)
#define Bsz 512
#define Dsz 128
#define Isz 64
#define Hd  256           // decoder hidden
#define HeN 512           // encoder hidden
#define KeTOT (Isz + HeN) // 576

// ---------------- device scratch (static, no allocations) ----------------
__device__ __nv_bfloat16 g_We_hi[4 * HeN][KeTOT];  // [n'=u*4+g][k]
__device__ __nv_bfloat16 g_We_lo[4 * HeN][KeTOT];
__device__ __nv_bfloat16 g_Wd_hi[4 * Hd][Hd];
__device__ __nv_bfloat16 g_Wd_lo[4 * Hd][Hd];
__device__ __nv_bfloat16 g_Wo_hi[Isz][Hd];         // Wout^T split, [n][k]
__device__ __nv_bfloat16 g_Wo_lo[Isz][Hd];
__device__ __nv_bfloat16 g_Xe_hi[Dsz][Bsz][Isz];   // X_imp split, [t][m][k]
__device__ __nv_bfloat16 g_Xe_lo[Dsz][Bsz][Isz];
__device__ __nv_bfloat16 g_he_hi[2][Bsz][HeN];     // encoder h ping-pong (split)
__device__ __nv_bfloat16 g_he_lo[2][Bsz][HeN];
__device__ __nv_bfloat16 g_hs_hi[Dsz][Bsz][Hd];    // decoder h sequence (split);
__device__ __nv_bfloat16 g_hs_lo[Dsz][Bsz][Hd];    //   doubles as the dec recurrence buffer
__device__ float g_c_d[Bsz * Hd];                  // decoder c0 (= z), read once
// dependency-scoped step barriers: one counter per bm-row group (256B stride)
__device__ unsigned int g_bar_eg[4][64];           // encoder: 32 CTAs per group
__device__ unsigned int g_bar_dg[8][64];           // decoder: 16 CTAs per group

// fast transcendentals (error ~1e-6 rel; budget is 1e-3, current rel_err 8e-6)
__device__ __forceinline__ float sigm(float x) {
    return __fdividef(1.0f, 1.0f + __expf(-x));
}
__device__ __forceinline__ float tanh_fast(float x) {
    return 1.0f - __fdividef(2.0f, __expf(2.0f * x) + 1.0f);
}

// ---------------- low-level helpers ----------------
__device__ __forceinline__ uint32_t smem_u32(const void* p) {
    uint32_t a;
    asm("{ .reg .u64 t; cvta.to.shared.u64 t, %1; cvt.u32.u64 %0, t; }" : "=r"(a) : "l"(p));
    return a;
}
#define CP16(dst, src) \
    asm volatile("cp.async.cg.shared.global [%0], [%1], 16;" :: "r"(dst), "l"(src) : "memory")
#define CP_COMMIT() asm volatile("cp.async.commit_group;" ::: "memory")
#define CP_WAIT1()  asm volatile("cp.async.wait_group 1;" ::: "memory")
#define CP_WAIT0()  asm volatile("cp.async.wait_group 0;" ::: "memory")

__device__ __forceinline__ void ldsm4(uint32_t* d, uint32_t addr) {
    asm volatile("ldmatrix.sync.aligned.m8n8.x4.shared.b16 {%0,%1,%2,%3}, [%4];"
        : "=r"(d[0]), "=r"(d[1]), "=r"(d[2]), "=r"(d[3]) : "r"(addr));
}
__device__ __forceinline__ void mma16816(float* c, const uint32_t* a, uint32_t b0, uint32_t b1) {
    asm volatile("mma.sync.aligned.m16n8k16.row.col.f32.bf16.bf16.f32 "
        "{%0,%1,%2,%3}, {%4,%5,%6,%7}, {%8,%9}, {%0,%1,%2,%3};"
        : "+f"(c[0]), "+f"(c[1]), "+f"(c[2]), "+f"(c[3])
        : "r"(a[0]), "r"(a[1]), "r"(a[2]), "r"(a[3]), "r"(b0), "r"(b1));
}

// 128B-row tiles with XOR swizzle (Swizzle<3,4,3>): bits[6:4] ^= bits[9:7]
__device__ __forceinline__ uint32_t swz(uint32_t off) { return off ^ ((off >> 3) & 0x70); }

// ---- encoder persistent layout (K-chunks of 64) ----
#define E_WCH   16384                    // weight chunk: 64 rows x 128B, hi + lo
#define E_WS_SZ (9 * E_WCH)              // 147456 B resident weights
#define E_AST   32768                    // A stage: 128 rows x 128B, hi + lo
#define E_A0    E_WS_SZ
#define E_CONST (E_A0 + 2 * E_AST)       // 212992
#define E_HST   (E_CONST + 512)          // h staging: 128x16 bf16 hi (4KB) + lo (4KB)
#define E_SMEMP (E_HST + 8192)           // 221696 B
// ---- decoder persistent layout ----
#define D_WCH   16384
#define D_WS_SZ (4 * D_WCH)              // 65536 B
#define D_AST   16384                    // 64 rows x 128B, hi + lo
#define D_A0    D_WS_SZ
#define D_CONST (D_A0 + 2 * D_AST)       // 98304
#define D_HST   (D_CONST + 512)          // hi 2KB + lo 2KB
#define D_SMEMP (D_HST + 4096)           // 102912 B
// ---- out_mma layout: Wout resident (4 chunks) + A stages ----
#define OM_WCH  16384
#define OM_WS   (4 * OM_WCH)             // 65536
#define OM_AST  32768                    // 128 rows x 128B, hi + lo
#define OM_A0   OM_WS
#define OM_CONST (OM_A0 + 2 * OM_AST)    // 131072
#define OM_SMEM (OM_CONST + 256)         // 131328

// ---------------- prep kernels ----------------
__global__ void conv_We_kernel(const float* __restrict__ Wx, const float* __restrict__ Wh) {
    int idx = blockIdx.x * 256 + threadIdx.x;
    if (idx >= 4 * HeN * KeTOT) return;
    int n = idx / KeTOT, k = idx % KeTOT;
    int u = n >> 2, g = n & 3, col = g * HeN + u;
    float w = (k < Isz) ? Wx[k * (4 * HeN) + col] : Wh[(k - Isz) * (4 * HeN) + col];
    __nv_bfloat16 hi = __float2bfloat16(w);
    g_We_hi[n][k] = hi;
    g_We_lo[n][k] = __float2bfloat16(w - __bfloat162float(hi));
}
__global__ void conv_Wd_kernel(const float* __restrict__ Wh, const float* __restrict__ Wout) {
    int idx = blockIdx.x * 256 + threadIdx.x;
    if (idx < Isz * Hd) {
        int n = idx / Hd, k = idx % Hd;
        float w = Wout[k * Isz + n];
        __nv_bfloat16 hi = __float2bfloat16(w);
        g_Wo_hi[n][k] = hi;
        g_Wo_lo[n][k] = __float2bfloat16(w - __bfloat162float(hi));
    }
    if (idx >= 4 * Hd * Hd) return;
    int n = idx / Hd, k = idx % Hd;
    int u = n >> 2, g = n & 3, col = g * Hd + u;
    float w = Wh[k * (4 * Hd) + col];
    __nv_bfloat16 hi = __float2bfloat16(w);
    g_Wd_hi[n][k] = hi;
    g_Wd_lo[n][k] = __float2bfloat16(w - __bfloat162float(hi));
}
__global__ void conv_X_kernel(const float* __restrict__ X, const float* __restrict__ Wm,
                              const float* __restrict__ A) {
    int idx = blockIdx.x * 256 + threadIdx.x;
    if (idx >= Dsz * Bsz * Isz) return;
    int t = idx / (Bsz * Isz);
    int r = idx % (Bsz * Isz);
    int m = r / Isz, k = r % Isz;
    int src = (m * Dsz + t) * Isz + k;
    float w = Wm[src];
    float v = X[src] * w + A[t * Isz + k] * (1.0f - w);
    __nv_bfloat16 hi = __float2bfloat16(v);
    g_Xe_hi[t][m][k] = hi;
    g_Xe_lo[t][m][k] = __float2bfloat16(v - __bfloat162float(hi));
}
__global__ void init_enc_kernel() {
    int i = blockIdx.x * 256 + threadIdx.x;
    if (i < 4) g_bar_eg[i][0] = 0u;
    if (i < 8) g_bar_dg[i][0] = 0u;
    if (i >= Bsz * HeN) return;
    __nv_bfloat16 z = __float2bfloat16(0.0f);
    (&g_he_hi[0][0][0])[i] = z;
    (&g_he_lo[0][0][0])[i] = z;
}

// ---------------- small outputs (accurate math; negligible cost) ----------------
__global__ void small_kernel(const float* __restrict__ mu_c_raw,
                             const float* __restrict__ sig_lat,
                             const float* __restrict__ phi_lat,
                             float* __restrict__ out_muc,
                             float* __restrict__ out_sig,
                             float* __restrict__ out_phi) {
    int tid = threadIdx.x;
    for (int i = tid; i < 8 * Hd; i += blockDim.x) {
        out_muc[i] = mu_c_raw[i];
        float v = sig_lat[i];
        out_sig[i] = fmaxf(v, 0.0f) + log1pf(expf(-fabsf(v)));
    }
    if (tid == 0) {
        float m = -1e30f;
        for (int i = 0; i < 8; ++i) m = fmaxf(m, phi_lat[i]);
        float e[8]; float s = 0.0f;
        for (int i = 0; i < 8; ++i) { e[i] = expf(phi_lat[i] - m); s += e[i]; }
        float inv = 1.0f / s;
        for (int i = 0; i < 8; ++i) out_phi[i] = e[i] * inv;
    }
}

// ============================================================================
// Persistent encoder: grid (4, 32), 256 threads (8 warps), 1 CTA/SM.
// CTA tile M=128, N=64. Warp: rows (wid&3)*32, cols (wid>>2)*32.
// K-chunks of 64 (9 chunks). Swizzled 128B tiles. Fragment-layout gates;
// c register-resident; per-bm-group step barrier (32 CTAs per group).
// ============================================================================
__global__ void __launch_bounds__(256, 1) enc_persist(
    const float* __restrict__ bias,
    const float* __restrict__ wci, const float* __restrict__ wcf,
    const float* __restrict__ wco) {
    extern __shared__ char smem[];
    const uint32_t sb = smem_u32(smem);
    const int tid = threadIdx.x, wid = tid >> 5, lane = tid & 31;
    const int rw = wid & 3, cw = wid >> 2;
    const int bm0 = blockIdx.x * 128;
    const int n0  = blockIdx.y * 64;
    const int U0  = n0 >> 2;
    unsigned int* mybar = &g_bar_eg[blockIdx.x][0];

    // ---- one-time: resident weight slab ----
#pragma unroll
    for (int c = 0; c < 9; ++c) {
        uint32_t wb = sb + c * E_WCH;
#pragma unroll
        for (int j = 0; j < 2; ++j) {
            int flat = tid + j * 256;
            int row = flat >> 3, c16 = flat & 7;
            uint32_t off = swz(row * 128 + c16 * 16);
            CP16(wb + off,        &g_We_hi[n0 + row][c * 64 + c16 * 8]);
            CP16(wb + 8192 + off, &g_We_lo[n0 + row][c * 64 + c16 * 8]);
        }
    }
    CP_COMMIT();
    float* csm = (float*)(smem + E_CONST);
    if (tid < 16) {
        int u = U0 + tid;
        csm[tid]      = bias[u];
        csm[16 + tid] = bias[HeN + u];
        csm[32 + tid] = bias[2 * HeN + u];
        csm[48 + tid] = bias[3 * HeN + u];
        csm[64 + tid] = wci[u];
        csm[80 + tid] = wcf[u];
        csm[96 + tid] = wco[u];
    }
    CP_WAIT0();
    __syncthreads();

#define E_AISSUE(ah_, al_, ap_, kb_, s_) do { \
        uint32_t so_ = sb + E_A0 + (s_) * E_AST; \
        _Pragma("unroll") \
        for (int j = 0; j < 4; ++j) { \
            int flat = tid + j * 256; \
            int row = flat >> 3, c16 = flat & 7; \
            uint32_t off = swz(row * 128 + c16 * 16); \
            CP16(so_ + off,         (ah_) + (bm0 + row) * (ap_) + (kb_) + c16 * 8); \
            CP16(so_ + 16384 + off, (al_) + (bm0 + row) * (ap_) + (kb_) + c16 * 8); \
        } \
    } while (0)

    E_AISSUE((&g_Xe_hi[0][0][0]), (&g_Xe_lo[0][0][0]), Isz, 0, 0);
    CP_COMMIT();

    const int a_row = (lane & 7) + ((lane >> 3) & 1) * 8;
    const int a_kb  = ((lane >> 4) & 1) * 16;
    const int b_row = (lane & 7) + (lane >> 4) * 8;
    const int b_kb  = ((lane >> 3) & 1) * 16;
    const uint32_t lxor = (uint32_t)((lane & 7) << 4);
    const int q = lane & 3;
    const bool evn = (q & 1) == 0;
    unsigned short* hsh = (unsigned short*)(smem + E_HST);
    unsigned short* hsl = (unsigned short*)(smem + E_HST + 4096);

    float creg[8] = {0.f, 0.f, 0.f, 0.f, 0.f, 0.f, 0.f, 0.f};

    for (int t = 0; t < Dsz; ++t) {
        const int buf = t & 1;
        const __nv_bfloat16* __restrict__ hhi = &g_he_hi[buf][0][0];
        const __nv_bfloat16* __restrict__ hlo = &g_he_lo[buf][0][0];

        E_AISSUE(hhi, hlo, HeN, 0, 1);
        CP_COMMIT();

        float acc[2][4][4];
#pragma unroll
        for (int mt = 0; mt < 2; ++mt)
#pragma unroll
            for (int nt = 0; nt < 4; ++nt)
#pragma unroll
                for (int r = 0; r < 4; ++r) acc[mt][nt][r] = 0.0f;

        for (int c = 0; c < 9; ++c) {
            CP_WAIT1();
            __syncthreads();
            const uint32_t so = sb + E_A0 + (c & 1) * E_AST;
            const uint32_t wb = sb + c * E_WCH;
#pragma unroll
            for (int ks = 0; ks < 4; ++ks) {
                uint32_t Ah[2][4], Al[2][4], Bh[2][4], Bl[2][4];
#pragma unroll
                for (int mt = 0; mt < 2; ++mt) {
                    uint32_t ra = so + (uint32_t)(rw * 32 + mt * 16 + a_row) * 128
                                + (((uint32_t)(ks * 32 + a_kb)) ^ lxor);
                    ldsm4(Ah[mt], ra);
                    ldsm4(Al[mt], ra + 16384);
                }
#pragma unroll
                for (int np = 0; np < 2; ++np) {
                    uint32_t rb = wb + (uint32_t)(cw * 32 + np * 16 + b_row) * 128
                                + (((uint32_t)(ks * 32 + b_kb)) ^ lxor);
                    ldsm4(Bh[np], rb);
                    ldsm4(Bl[np], rb + 8192);
                }
#pragma unroll
                for (int mt = 0; mt < 2; ++mt)
#pragma unroll
                    for (int np = 0; np < 2; ++np) {
                        mma16816(acc[mt][2 * np],     Ah[mt], Bh[np][0], Bh[np][1]);
                        mma16816(acc[mt][2 * np + 1], Ah[mt], Bh[np][2], Bh[np][3]);
                        mma16816(acc[mt][2 * np],     Ah[mt], Bl[np][0], Bl[np][1]);
                        mma16816(acc[mt][2 * np + 1], Ah[mt], Bl[np][2], Bl[np][3]);
                        mma16816(acc[mt][2 * np],     Al[mt], Bh[np][0], Bh[np][1]);
                        mma16816(acc[mt][2 * np + 1], Al[mt], Bh[np][2], Bh[np][3]);
                    }
            }
            __syncthreads();
            if (c + 2 <= 8) {
                E_AISSUE(hhi, hlo, HeN, (c + 1) * 64, (c & 1));
            }
            CP_COMMIT();
        }
        CP_WAIT0();

        // ---- gates directly in fragment layout ----
#pragma unroll
        for (int mt = 0; mt < 2; ++mt)
#pragma unroll
            for (int nt = 0; nt < 4; ++nt) {
                float a0 = acc[mt][nt][0], a1 = acc[mt][nt][1];
                float a2 = acc[mt][nt][2], a3 = acc[mt][nt][3];
                float v0 = __shfl_xor_sync(0xffffffffu, evn ? a2 : a0, 1);
                float v1 = __shfl_xor_sync(0xffffffffu, evn ? a3 : a1, 1);
                float zi = evn ? a0 : v0;
                float zf = evn ? a1 : v1;
                float zg = evn ? v0 : a2;
                float zo = evn ? v1 : a3;
                int ul = cw * 8 + nt * 2 + (q >> 1);
                int myrow = rw * 32 + mt * 16 + (lane >> 2) + (evn ? 0 : 8);
                float c_old = creg[mt * 4 + nt];
                zi += csm[ul]; zf += csm[16 + ul]; zg += csm[32 + ul]; zo += csm[48 + ul];
                float ig = sigm(zi + c_old * csm[64 + ul]);
                float fg = sigm(zf + c_old * csm[80 + ul]);
                float cn = fg * c_old + ig * tanh_fast(zg);
                float og = sigm(zo + cn * csm[96 + ul]);
                float h  = og * tanh_fast(cn);
                creg[mt * 4 + nt] = cn;
                __nv_bfloat16 hb = __float2bfloat16(h);
                hsh[myrow * 16 + ul] = __bfloat16_as_ushort(hb);
                hsl[myrow * 16 + ul] = __bfloat16_as_ushort(__float2bfloat16(h - __bfloat162float(hb)));
            }
        __syncthreads();

        // ---- coalesced h copy-out ----
        {
            int r = tid & 127;
            const uint4* src = (const uint4*)((tid < 128 ? (char*)hsh : (char*)hsl) + r * 32);
            uint4* dst = (tid < 128) ? (uint4*)&g_he_hi[buf ^ 1][bm0 + r][U0]
                                     : (uint4*)&g_he_lo[buf ^ 1][bm0 + r][U0];
            dst[0] = src[0];
            dst[1] = src[1];
        }

        if (t + 1 < Dsz) {
            E_AISSUE((&g_Xe_hi[t + 1][0][0]), (&g_Xe_lo[t + 1][0][0]), Isz, 0, 0);
            CP_COMMIT();

            __threadfence();
            __syncthreads();
            if (tid == 0) {
                atomicAdd(mybar, 1u);
                unsigned int target = 32u * (unsigned int)(t + 1);
                while (*(volatile unsigned int*)mybar < target) { }
                __threadfence();
            }
            __syncthreads();
        }
    }
#undef E_AISSUE
}

// ---------------- latent z + decoder init ----------------
__global__ void z_kernel(const float* __restrict__ noise,
                         float* __restrict__ out_z,
                         float* __restrict__ out_mu,
                         float* __restrict__ out_ls) {
    int idx = blockIdx.x * blockDim.x + threadIdx.x;
    if (idx >= Bsz * Hd) return;
    int b = idx >> 8;
    int u = idx & 255;
    float mu = __bfloat162float(g_he_hi[0][b][u]) + __bfloat162float(g_he_lo[0][b][u]);
    float ls = __bfloat162float(g_he_hi[0][b][Hd + u]) + __bfloat162float(g_he_lo[0][b][Hd + u]);
    float zz = mu + expf(0.5f * ls) * noise[idx];
    out_mu[idx] = mu;
    out_ls[idx] = ls;
    out_z[idx]  = zz;
    g_c_d[idx]  = zz;
}

// ============================================================================
// Persistent decoder: grid (8, 16), 256 threads (8 warps), 1 CTA/SM.
// CTA tile M=64, N=64. K-chunks of 64 (4 chunks). Fragment-layout gates;
// c register-resident. h sequence stored split-bf16 in g_hs_hi/lo[t],
// which also serves as the recurrence buffer (reads step t-1).
// ============================================================================
__global__ void __launch_bounds__(256, 1) dec_persist(
    const float* __restrict__ bias,
    const float* __restrict__ wci, const float* __restrict__ wcf,
    const float* __restrict__ wco) {
    extern __shared__ char smem[];
    const uint32_t sb = smem_u32(smem);
    const int tid = threadIdx.x, wid = tid >> 5, lane = tid & 31;
    const int rw = wid & 1, cw = wid >> 1;
    const int bm0 = blockIdx.x * 64;
    const int n0  = blockIdx.y * 64;
    const int U0  = n0 >> 2;
    unsigned int* mybar = &g_bar_dg[blockIdx.x][0];

    // ---- one-time: resident weight slab ----
#pragma unroll
    for (int c = 0; c < 4; ++c) {
        uint32_t wb = sb + c * D_WCH;
#pragma unroll
        for (int j = 0; j < 2; ++j) {
            int flat = tid + j * 256;
            int row = flat >> 3, c16 = flat & 7;
            uint32_t off = swz(row * 128 + c16 * 16);
            CP16(wb + off,        &g_Wd_hi[n0 + row][c * 64 + c16 * 8]);
            CP16(wb + 8192 + off, &g_Wd_lo[n0 + row][c * 64 + c16 * 8]);
        }
    }
    CP_COMMIT();
    float* csm = (float*)(smem + D_CONST);
    if (tid < 16) {
        int u = U0 + tid;
        csm[tid]      = bias[u];
        csm[16 + tid] = bias[Hd + u];
        csm[32 + tid] = bias[2 * Hd + u];
        csm[48 + tid] = bias[3 * Hd + u];
        csm[64 + tid] = wci[u];
        csm[80 + tid] = wcf[u];
        csm[96 + tid] = wco[u];
    }
    CP_WAIT0();
    __syncthreads();

    const int a_row = (lane & 7) + ((lane >> 3) & 1) * 8;
    const int a_kb  = ((lane >> 4) & 1) * 16;
    const int b_row = (lane & 7) + (lane >> 4) * 8;
    const int b_kb  = ((lane >> 3) & 1) * 16;
    const uint32_t lxor = (uint32_t)((lane & 7) << 4);
    const int q = lane & 3;
    const bool evn = (q & 1) == 0;
    unsigned short* hsh = (unsigned short*)(smem + D_HST);
    unsigned short* hsl = (unsigned short*)(smem + D_HST + 2048);

    // register-resident c in fragment layout; c0 = z
    float creg[4];
#pragma unroll
    for (int mt = 0; mt < 2; ++mt)
#pragma unroll
        for (int nt = 0; nt < 2; ++nt) {
            int ul = cw * 4 + nt * 2 + (q >> 1);
            int myrow = rw * 32 + mt * 16 + (lane >> 2) + (evn ? 0 : 8);
            creg[mt * 2 + nt] = g_c_d[(bm0 + myrow) * Hd + U0 + ul];
        }

    for (int t = 0; t < Dsz; ++t) {
        float acc[2][2][4];
#pragma unroll
        for (int mt = 0; mt < 2; ++mt)
#pragma unroll
            for (int nt = 0; nt < 2; ++nt)
#pragma unroll
                for (int r = 0; r < 4; ++r) acc[mt][nt][r] = 0.0f;

        if (t > 0) {
            const __nv_bfloat16* __restrict__ hhi = &g_hs_hi[t - 1][0][0];
            const __nv_bfloat16* __restrict__ hlo = &g_hs_lo[t - 1][0][0];

#define D_AISSUE(c, s) do { \
            uint32_t so_ = sb + D_A0 + (s) * D_AST; \
            int kb_ = (c) * 64; \
            _Pragma("unroll") \
            for (int j = 0; j < 2; ++j) { \
                int flat = tid + j * 256; \
                int row = flat >> 3, c16 = flat & 7; \
                uint32_t off = swz(row * 128 + c16 * 16); \
                CP16(so_ + off,        hhi + (bm0 + row) * Hd + kb_ + c16 * 8); \
                CP16(so_ + 8192 + off, hlo + (bm0 + row) * Hd + kb_ + c16 * 8); \
            } \
        } while (0)

            D_AISSUE(0, 0); CP_COMMIT();
            D_AISSUE(1, 1); CP_COMMIT();

            for (int c = 0; c < 4; ++c) {
                CP_WAIT1();
                __syncthreads();
                const uint32_t so = sb + D_A0 + (c & 1) * D_AST;
                const uint32_t wb = sb + c * D_WCH;
#pragma unroll
                for (int ks = 0; ks < 4; ++ks) {
                    uint32_t Ah[2][4], Al[2][4], Bh[4], Bl[4];
#pragma unroll
                    for (int mt = 0; mt < 2; ++mt) {
                        uint32_t ra = so + (uint32_t)(rw * 32 + mt * 16 + a_row) * 128
                                    + (((uint32_t)(ks * 32 + a_kb)) ^ lxor);
                        ldsm4(Ah[mt], ra);
                        ldsm4(Al[mt], ra + 8192);
                    }
                    uint32_t rb = wb + (uint32_t)(cw * 16 + b_row) * 128
                                + (((uint32_t)(ks * 32 + b_kb)) ^ lxor);
                    ldsm4(Bh, rb);
                    ldsm4(Bl, rb + 8192);
#pragma unroll
                    for (int mt = 0; mt < 2; ++mt) {
                        mma16816(acc[mt][0], Ah[mt], Bh[0], Bh[1]);
                        mma16816(acc[mt][1], Ah[mt], Bh[2], Bh[3]);
                        mma16816(acc[mt][0], Ah[mt], Bl[0], Bl[1]);
                        mma16816(acc[mt][1], Ah[mt], Bl[2], Bl[3]);
                        mma16816(acc[mt][0], Al[mt], Bh[0], Bh[1]);
                        mma16816(acc[mt][1], Al[mt], Bh[2], Bh[3]);
                    }
                }
                __syncthreads();
                if (c + 2 <= 3) { D_AISSUE(c + 2, c & 1); }
                CP_COMMIT();
            }
#undef D_AISSUE
            CP_WAIT0();
        }

        // ---- gates in fragment layout ----
#pragma unroll
        for (int mt = 0; mt < 2; ++mt)
#pragma unroll
            for (int nt = 0; nt < 2; ++nt) {
                float a0 = acc[mt][nt][0], a1 = acc[mt][nt][1];
                float a2 = acc[mt][nt][2], a3 = acc[mt][nt][3];
                float v0 = __shfl_xor_sync(0xffffffffu, evn ? a2 : a0, 1);
                float v1 = __shfl_xor_sync(0xffffffffu, evn ? a3 : a1, 1);
                float zi = evn ? a0 : v0;
                float zf = evn ? a1 : v1;
                float zg = evn ? v0 : a2;
                float zo = evn ? v1 : a3;
                int ul = cw * 4 + nt * 2 + (q >> 1);
                int myrow = rw * 32 + mt * 16 + (lane >> 2) + (evn ? 0 : 8);
                float c_old = creg[mt * 2 + nt];
                zi += csm[ul]; zf += csm[16 + ul]; zg += csm[32 + ul]; zo += csm[48 + ul];
                float ig = sigm(zi + c_old * csm[64 + ul]);
                float fg = sigm(zf + c_old * csm[80 + ul]);
                float cn = fg * c_old + ig * tanh_fast(zg);
                float og = sigm(zo + cn * csm[96 + ul]);
                float h  = og * tanh_fast(cn);
                creg[mt * 2 + nt] = cn;
                __nv_bfloat16 hb = __float2bfloat16(h);
                hsh[myrow * 16 + ul] = __bfloat16_as_ushort(hb);
                hsl[myrow * 16 + ul] = __bfloat16_as_ushort(__float2bfloat16(h - __bfloat162float(hb)));
            }
        __syncthreads();

        // ---- coalesced copy-out to the h sequence (also recurrence buffer) ----
        if (tid < 64) {
            int r = tid;
            const uint4* src = (const uint4*)((char*)hsh + r * 32);
            uint4* dst = (uint4*)&g_hs_hi[t][bm0 + r][U0];
            dst[0] = src[0]; dst[1] = src[1];
        } else if (tid < 128) {
            int r = tid - 64;
            const uint4* src = (const uint4*)((char*)hsl + r * 32);
            uint4* dst = (uint4*)&g_hs_lo[t][bm0 + r][U0];
            dst[0] = src[0]; dst[1] = src[1];
        }

        if (t + 1 < Dsz) {
            __threadfence();
            __syncthreads();
            if (tid == 0) {
                atomicAdd(mybar, 1u);
                unsigned int target = 16u * (unsigned int)(t + 1);
                while (*(volatile unsigned int*)mybar < target) { }
                __threadfence();
            }
            __syncthreads();
        }
    }
}

// ============================================================================
// Output projection via HMMA: out = hs @ Wout + bout; x = sigm(out).
// grid (Dsz, 4), 256 threads. CTA: M=128 batch rows, N=64 cols, K=256.
// Wout hi/lo resident in smem; hs streamed via 2-stage cp.async; 3-pass split.
// ============================================================================
__global__ void __launch_bounds__(256) out_mma(
    const float* __restrict__ bout,
    float* __restrict__ out_x, float* __restrict__ out_xraw) {
    extern __shared__ char smem[];
    const uint32_t sb = smem_u32(smem);
    const int tid = threadIdx.x, wid = tid >> 5, lane = tid & 31;
    const int rw = wid & 3, cw = wid >> 2;
    const int t   = blockIdx.x;
    const int bm0 = blockIdx.y * 128;

    // resident Wout slab (64 rows x 256 k, hi+lo, 4 chunks)
#pragma unroll
    for (int c = 0; c < 4; ++c) {
        uint32_t wb = sb + c * OM_WCH;
#pragma unroll
        for (int j = 0; j < 2; ++j) {
            int flat = tid + j * 256;
            int row = flat >> 3, c16 = flat & 7;
            uint32_t off = swz(row * 128 + c16 * 16);
            CP16(wb + off,        &g_Wo_hi[row][c * 64 + c16 * 8]);
            CP16(wb + 8192 + off, &g_Wo_lo[row][c * 64 + c16 * 8]);
        }
    }
    CP_COMMIT();
    float* csm = (float*)(smem + OM_CONST);
    if (tid < 64) csm[tid] = bout[tid];

#define O_AISSUE(c, s) do { \
        uint32_t so_ = sb + OM_A0 + (s) * OM_AST; \
        int kb_ = (c) * 64; \
        _Pragma("unroll") \
        for (int j = 0; j < 4; ++j) { \
            int flat = tid + j * 256; \
            int row = flat >> 3, c16 = flat & 7; \
            uint32_t off = swz(row * 128 + c16 * 16); \
            CP16(so_ + off,         &g_hs_hi[t][bm0 + row][kb_ + c16 * 8]); \
            CP16(so_ + 16384 + off, &g_hs_lo[t][bm0 + row][kb_ + c16 * 8]); \
        } \
    } while (0)

    O_AISSUE(0, 0); CP_COMMIT();
    O_AISSUE(1, 1); CP_COMMIT();

    const int a_row = (lane & 7) + ((lane >> 3) & 1) * 8;
    const int a_kb  = ((lane >> 4) & 1) * 16;
    const int b_row = (lane & 7) + (lane >> 4) * 8;
    const int b_kb  = ((lane >> 3) & 1) * 16;
    const uint32_t lxor = (uint32_t)((lane & 7) << 4);
    const int q = lane & 3;

    float acc[2][4][4];
#pragma unroll
    for (int mt = 0; mt < 2; ++mt)
#pragma unroll
        for (int nt = 0; nt < 4; ++nt)
#pragma unroll
            for (int r = 0; r < 4; ++r) acc[mt][nt][r] = 0.0f;

    for (int c = 0; c < 4; ++c) {
        CP_WAIT1();
        __syncthreads();
        const uint32_t so = sb + OM_A0 + (c & 1) * OM_AST;
        const uint32_t wb = sb + c * OM_WCH;
#pragma unroll
        for (int ks = 0; ks < 4; ++ks) {
            uint32_t Ah[2][4], Al[2][4], Bh[2][4], Bl[2][4];
#pragma unroll
            for (int mt = 0; mt < 2; ++mt) {
                uint32_t ra = so + (uint32_t)(rw * 32 + mt * 16 + a_row) * 128
                            + (((uint32_t)(ks * 32 + a_kb)) ^ lxor);
                ldsm4(Ah[mt], ra);
                ldsm4(Al[mt], ra + 16384);
            }
#pragma unroll
            for (int np = 0; np < 2; ++np) {
                uint32_t rb = wb + (uint32_t)(cw * 32 + np * 16 + b_row) * 128
                            + (((uint32_t)(ks * 32 + b_kb)) ^ lxor);
                ldsm4(Bh[np], rb);
                ldsm4(Bl[np], rb + 8192);
            }
#pragma unroll
            for (int mt = 0; mt < 2; ++mt)
#pragma unroll
                for (int np = 0; np < 2; ++np) {
                    mma16816(acc[mt][2 * np],     Ah[mt], Bh[np][0], Bh[np][1]);
                    mma16816(acc[mt][2 * np + 1], Ah[mt], Bh[np][2], Bh[np][3]);
                    mma16816(acc[mt][2 * np],     Ah[mt], Bl[np][0], Bl[np][1]);
                    mma16816(acc[mt][2 * np + 1], Ah[mt], Bl[np][2], Bl[np][3]);
                    mma16816(acc[mt][2 * np],     Al[mt], Bh[np][0], Bh[np][1]);
                    mma16816(acc[mt][2 * np + 1], Al[mt], Bh[np][2], Bh[np][3]);
                }
        }
        __syncthreads();
        if (c + 2 <= 3) { O_AISSUE(c + 2, c & 1); }
        CP_COMMIT();
    }
#undef O_AISSUE

    // ---- epilogue: bias + sigmoid, direct fragment stores ----
#pragma unroll
    for (int mt = 0; mt < 2; ++mt)
#pragma unroll
        for (int nt = 0; nt < 4; ++nt) {
            int col = cw * 32 + nt * 8 + q * 2;
            float b0 = csm[col], b1 = csm[col + 1];
            int r0 = bm0 + rw * 32 + mt * 16 + (lane >> 2);
#pragma unroll
            for (int hh = 0; hh < 2; ++hh) {
                int row = r0 + hh * 8;
                float x0 = acc[mt][nt][2 * hh]     + b0;
                float x1 = acc[mt][nt][2 * hh + 1] + b1;
                int oi = (row * Dsz + t) * Isz + col;
                *(float2*)&out_xraw[oi] = make_float2(x0, x1);
                *(float2*)&out_x[oi]    = make_float2(sigm(x0), sigm(x1));
            }
        }
}

// ---------------- launch ----------------
extern "C" void kernel_launch(void* const* d_in, const int* in_sizes, int n_in,
                              void* d_out, int out_size) {
    (void)in_sizes; (void)n_in; (void)out_size;
    const float* X      = (const float*)d_in[0];
    const float* Wm     = (const float*)d_in[1];
    const float* noise  = (const float*)d_in[2];
    const float* A      = (const float*)d_in[3];
    const float* Wx_e   = (const float*)d_in[4];
    const float* Wh_e   = (const float*)d_in[5];
    const float* b_e    = (const float*)d_in[6];
    const float* wci_e  = (const float*)d_in[7];
    const float* wcf_e  = (const float*)d_in[8];
    const float* wco_e  = (const float*)d_in[9];
    // d_in[10] = Wx_d : unused (decoder inputs are zero)
    const float* Wh_d   = (const float*)d_in[11];
    const float* b_d    = (const float*)d_in[12];
    const float* wci_d  = (const float*)d_in[13];
    const float* wcf_d  = (const float*)d_in[14];
    const float* wco_d  = (const float*)d_in[15];
    const float* Wout   = (const float*)d_in[16];
    const float* bout   = (const float*)d_in[17];
    const float* mu_c_r = (const float*)d_in[18];
    const float* sig_l  = (const float*)d_in[19];
    const float* phi_l  = (const float*)d_in[20];

    float* out = (float*)d_out;
    float* out_x    = out;                 // 4194304
    float* out_xraw = out + 4194304;       // 4194304
    float* out_muc  = out + 8388608;       // 2048
    float* out_sig  = out + 8390656;       // 2048
    float* out_phi  = out + 8392704;       // 8
    float* out_z    = out + 8392712;       // 131072
    float* out_mu   = out + 8523784;       // 131072
    float* out_ls   = out + 8654856;       // 131072

    cudaFuncSetAttribute(enc_persist, cudaFuncAttributeMaxDynamicSharedMemorySize, E_SMEMP);
    cudaFuncSetAttribute(dec_persist, cudaFuncAttributeMaxDynamicSharedMemorySize, D_SMEMP);
    cudaFuncSetAttribute(out_mma,     cudaFuncAttributeMaxDynamicSharedMemorySize, OM_SMEM);

    conv_We_kernel<<<(4 * HeN * KeTOT + 255) / 256, 256>>>(Wx_e, Wh_e);
    conv_Wd_kernel<<<(4 * Hd * Hd + 255) / 256, 256>>>(Wh_d, Wout);
    conv_X_kernel<<<(Dsz * Bsz * Isz + 255) / 256, 256>>>(X, Wm, A);
    init_enc_kernel<<<(Bsz * HeN + 255) / 256, 256>>>();
    small_kernel<<<1, 256>>>(mu_c_r, sig_l, phi_l, out_muc, out_sig, out_phi);

    enc_persist<<<dim3(4, 32), 256, E_SMEMP>>>(b_e, wci_e, wcf_e, wco_e);

    z_kernel<<<(Bsz * Hd + 255) / 256, 256>>>(noise, out_z, out_mu, out_ls);

    dec_persist<<<dim3(8, 16), 256, D_SMEMP>>>(b_d, wci_d, wcf_d, wco_d);

    out_mma<<<dim3(Dsz, 4), 256, OM_SMEM>>>(bout, out_x, out_xraw);
}